// round 6
// baseline (speedup 1.0000x reference)
#include <cuda_runtime.h>
#include <math.h>
#include <stdint.h>

#define BB 2
#define NSEQ 2048
#define NH 16
#define DH 64
#define DM 1024
#define KSEL 32

// ---------------- scratch (device globals; no cudaMalloc allowed) ----------
__device__ float g_q[(size_t)BB * NH * NSEQ * DH];     // 16.8 MB  [bh][n][d]
__device__ float g_k[(size_t)BB * NH * NSEQ * DH];     // 16.8 MB
__device__ float g_v[(size_t)BB * NH * NSEQ * DH];     // 16.8 MB
__device__ float g_o[(size_t)BB * NSEQ * DM];          // 16.8 MB  [b][n][h*64+d]
__device__ float g_s[(size_t)BB * NH * NSEQ * NSEQ];   // 536 MB   [bh][q][k]

// ---------------- warp helpers --------------------------------------------
__device__ __forceinline__ float warpMax(float v) {
#pragma unroll
    for (int o = 16; o; o >>= 1) v = fmaxf(v, __shfl_xor_sync(0xffffffffu, v, o));
    return v;
}
__device__ __forceinline__ float warpSum(float v) {
#pragma unroll
    for (int o = 16; o; o >>= 1) v += __shfl_xor_sync(0xffffffffu, v, o);
    return v;
}

// full bitonic sort of 32 (value,index) across a warp, descending by value
__device__ __forceinline__ void bsort32_desc(float& v, int& i, int lane) {
#pragma unroll
    for (int k = 2; k <= 32; k <<= 1) {
#pragma unroll
        for (int j = k >> 1; j > 0; j >>= 1) {
            float ov = __shfl_xor_sync(0xffffffffu, v, j);
            int   oi = __shfl_xor_sync(0xffffffffu, i, j);
            bool up    = ((lane & k) != 0);   // flipped -> overall descending
            bool lower = ((lane & j) == 0);
            bool take  = (lower == up) ? (ov < v) : (ov > v);
            if (take) { v = ov; i = oi; }
        }
    }
}

// bitonic clean (input bitonic) -> descending
__device__ __forceinline__ void bmerge32_desc(float& v, int& i, int lane) {
#pragma unroll
    for (int j = 16; j > 0; j >>= 1) {
        float ov = __shfl_xor_sync(0xffffffffu, v, j);
        int   oi = __shfl_xor_sync(0xffffffffu, i, j);
        bool lower = ((lane & j) == 0);
        bool take  = lower ? (ov > v) : (ov < v);
        if (take) { v = ov; i = oi; }
    }
}

// ---------------- zero fill ------------------------------------------------
__global__ void zero_kernel(float4* __restrict__ p, int n4) {
    int i = blockIdx.x * blockDim.x + threadIdx.x;
    int stride = gridDim.x * blockDim.x;
    float4 z = make_float4(0.f, 0.f, 0.f, 0.f);
    for (; i < n4; i += stride) p[i] = z;
}

// ---------------- QKV projection GEMM (x @ W^T + b), scatter per-head ------
// C[m][n] = sum_k x[m][k] * W[n][k];  M=4096, N=1024, K=1024
// 128x128 tile, BK=16, 256 threads, 8x8 micro (split 4+4 for conflict-free LDS)
__global__ __launch_bounds__(256) void qkv_gemm(
    const float* __restrict__ x,
    const float* __restrict__ Wq, const float* __restrict__ bq,
    const float* __restrict__ Wk, const float* __restrict__ bk,
    const float* __restrict__ Wv, const float* __restrict__ bv)
{
    const float* W; const float* bias; float* out;
    if (blockIdx.z == 0)      { W = Wq; bias = bq; out = g_q; }
    else if (blockIdx.z == 1) { W = Wk; bias = bk; out = g_k; }
    else                      { W = Wv; bias = bv; out = g_v; }

    __shared__ float As[16][132];
    __shared__ float Bs[16][132];

    const int tid = threadIdx.x;
    const int m0 = blockIdx.y * 128;
    const int n0 = blockIdx.x * 128;
    const int r  = (tid / 16) * 4;
    const int c  = (tid % 16) * 4;

    const int lrow = tid >> 1;               // 0..127
    const int lk0  = (tid & 1) * 8;          // 0 or 8

    float acc[8][8];
#pragma unroll
    for (int i = 0; i < 8; i++)
#pragma unroll
        for (int j = 0; j < 8; j++) acc[i][j] = 0.f;

    for (int k0 = 0; k0 < DM; k0 += 16) {
        // load A tile (x) transposed into As[k][m]
#pragma unroll
        for (int t = 0; t < 2; t++) {
            float4 a = *(const float4*)&x[(size_t)(m0 + lrow) * DM + k0 + lk0 + t * 4];
            int kk = lk0 + t * 4;
            As[kk + 0][lrow] = a.x; As[kk + 1][lrow] = a.y;
            As[kk + 2][lrow] = a.z; As[kk + 3][lrow] = a.w;
            float4 b = *(const float4*)&W[(size_t)(n0 + lrow) * DM + k0 + lk0 + t * 4];
            Bs[kk + 0][lrow] = b.x; Bs[kk + 1][lrow] = b.y;
            Bs[kk + 2][lrow] = b.z; Bs[kk + 3][lrow] = b.w;
        }
        __syncthreads();
#pragma unroll
        for (int kk = 0; kk < 16; kk++) {
            float4 a0 = *(const float4*)&As[kk][r];
            float4 a1 = *(const float4*)&As[kk][r + 64];
            float4 b0 = *(const float4*)&Bs[kk][c];
            float4 b1 = *(const float4*)&Bs[kk][c + 64];
            float av[8] = {a0.x, a0.y, a0.z, a0.w, a1.x, a1.y, a1.z, a1.w};
            float bw[8] = {b0.x, b0.y, b0.z, b0.w, b1.x, b1.y, b1.z, b1.w};
#pragma unroll
            for (int i = 0; i < 8; i++)
#pragma unroll
                for (int j = 0; j < 8; j++) acc[i][j] += av[i] * bw[j];
        }
        __syncthreads();
    }

    // scatter into [b][h][t][d]
#pragma unroll
    for (int i = 0; i < 8; i++) {
        int m = m0 + ((i < 4) ? (r + i) : (r + 64 + i - 4));
        int bIdx = m >> 11;                   // /2048
        int t = m & (NSEQ - 1);
#pragma unroll
        for (int j = 0; j < 8; j++) {
            int n = n0 + ((j < 4) ? (c + j) : (c + 64 + j - 4));
            int h = n >> 6;
            int d = n & 63;
            out[(((size_t)(bIdx * NH + h)) * NSEQ + t) * DH + d] = acc[i][j] + bias[n];
        }
    }
}

// ---------------- scores GEMM (lower-triangular tiles only) ----------------
// S[bh][q][k] = (Q[bh][q] . K[bh][k]) / 8, k<=q; diag tile k>q -> -inf
__global__ __launch_bounds__(256) void scores_gemm()
{
    // map blockIdx.x -> (qt, kt) over lower triangle of 16x16 tile grid
    int bx = blockIdx.x;
    int qt = 0;
    while ((qt + 1) * (qt + 2) / 2 <= bx) qt++;
    int kt = bx - qt * (qt + 1) / 2;
    const int bh = blockIdx.y;

    const float* Qb = g_q + (size_t)bh * NSEQ * DH;
    const float* Kb = g_k + (size_t)bh * NSEQ * DH;
    float* Sb = g_s + (size_t)bh * NSEQ * NSEQ;

    __shared__ float As[16][132];
    __shared__ float Bs[16][132];

    const int tid = threadIdx.x;
    const int q0 = qt * 128;
    const int k0b = kt * 128;
    const int r = (tid / 16) * 4;
    const int c = (tid % 16) * 4;
    const int lrow = tid >> 1;
    const int lk0  = (tid & 1) * 8;

    float acc[8][8];
#pragma unroll
    for (int i = 0; i < 8; i++)
#pragma unroll
        for (int j = 0; j < 8; j++) acc[i][j] = 0.f;

    for (int k0 = 0; k0 < DH; k0 += 16) {
#pragma unroll
        for (int t = 0; t < 2; t++) {
            float4 a = *(const float4*)&Qb[(size_t)(q0 + lrow) * DH + k0 + lk0 + t * 4];
            int kk = lk0 + t * 4;
            As[kk + 0][lrow] = a.x; As[kk + 1][lrow] = a.y;
            As[kk + 2][lrow] = a.z; As[kk + 3][lrow] = a.w;
            float4 b = *(const float4*)&Kb[(size_t)(k0b + lrow) * DH + k0 + lk0 + t * 4];
            Bs[kk + 0][lrow] = b.x; Bs[kk + 1][lrow] = b.y;
            Bs[kk + 2][lrow] = b.z; Bs[kk + 3][lrow] = b.w;
        }
        __syncthreads();
#pragma unroll
        for (int kk = 0; kk < 16; kk++) {
            float4 a0 = *(const float4*)&As[kk][r];
            float4 a1 = *(const float4*)&As[kk][r + 64];
            float4 b0 = *(const float4*)&Bs[kk][c];
            float4 b1 = *(const float4*)&Bs[kk][c + 64];
            float av[8] = {a0.x, a0.y, a0.z, a0.w, a1.x, a1.y, a1.z, a1.w};
            float bw[8] = {b0.x, b0.y, b0.z, b0.w, b1.x, b1.y, b1.z, b1.w};
#pragma unroll
            for (int i = 0; i < 8; i++)
#pragma unroll
                for (int j = 0; j < 8; j++) acc[i][j] += av[i] * bw[j];
        }
        __syncthreads();
    }

#pragma unroll
    for (int i = 0; i < 8; i++) {
        int q = q0 + ((i < 4) ? (r + i) : (r + 64 + i - 4));
#pragma unroll
        for (int j = 0; j < 8; j++) {
            int k = k0b + ((j < 4) ? (c + j) : (c + 64 + j - 4));
            float val = (k <= q) ? acc[i][j] * 0.125f : -INFINITY;
            Sb[(size_t)q * NSEQ + k] = val;
        }
    }
}

// ---------------- streaming warp top-32 + softmax + AV + scatter -----------
__global__ __launch_bounds__(256) void topk_attn(float* __restrict__ attn_out)
{
    const int wid = (blockIdx.x * blockDim.x + threadIdx.x) >> 5;
    const int lane = threadIdx.x & 31;
    if (wid >= BB * NH * NSEQ) return;
    const int q = wid & (NSEQ - 1);
    const int bh = wid >> 11;
    const int b = bh >> 4;
    const int h = bh & 15;

    const float* srow = g_s + ((size_t)bh * NSEQ + q) * NSEQ;
    const int nk = q + 1;

    float rv = -INFINITY; int ri = -1;
    float rmin = -INFINITY;

    for (int c0 = 0; c0 < nk; c0 += 32) {
        int j = c0 + lane;
        float v = (j < nk) ? srow[j] : -INFINITY;
        float cmax = warpMax(v);
        if (cmax > rmin) {
            int ii = j;
            bsort32_desc(v, ii, lane);
            // reversed-chunk elementwise max -> bitonic, then clean
            float ov = __shfl_xor_sync(0xffffffffu, v, 31);
            int   oi = __shfl_xor_sync(0xffffffffu, ii, 31);
            if (ov > rv) { rv = ov; ri = oi; }
            bmerge32_desc(rv, ri, lane);
            rmin = __shfl_sync(0xffffffffu, rv, 31);
        }
    }

    // softmax over kept 32 (rv=-inf entries contribute exactly 0)
    float m = __shfl_sync(0xffffffffu, rv, 0);   // lane0 = max, always finite
    float e = __expf ? expf(rv - m) : 0.f;       // expf(-inf)=0
    float s = warpSum(e);
    float p = e / s;

    // out = sum_j p_j * V[idx_j]; lane covers dims {lane, lane+32}
    float acc0 = 0.f, acc1 = 0.f;
#pragma unroll 8
    for (int t = 0; t < 32; t++) {
        float pt = __shfl_sync(0xffffffffu, p, t);
        int   it = __shfl_sync(0xffffffffu, ri, t);
        if (pt > 0.f && it >= 0) {
            const float* vr = g_v + ((size_t)bh * NSEQ + it) * DH;
            acc0 += pt * vr[lane];
            acc1 += pt * vr[lane + 32];
        }
    }
    size_t obase = ((size_t)(b * NSEQ + q)) * DM + h * DH;
    g_o[obase + lane]      = acc0;
    g_o[obase + lane + 32] = acc1;

    // attn.mean over heads: scatter p/16 (exact zeros elsewhere)
    if (ri >= 0 && p > 0.f)
        atomicAdd(&attn_out[((size_t)b * NSEQ + q) * NSEQ + ri], p * (1.f / 16.f));
}

// ---------------- output projection: y = O @ Wo^T + bo ---------------------
__global__ __launch_bounds__(256) void out_gemm(
    const float* __restrict__ Wo, const float* __restrict__ bo,
    float* __restrict__ y)
{
    __shared__ float As[16][132];
    __shared__ float Bs[16][132];

    const int tid = threadIdx.x;
    const int m0 = blockIdx.y * 128;
    const int n0 = blockIdx.x * 128;
    const int r = (tid / 16) * 4;
    const int c = (tid % 16) * 4;
    const int lrow = tid >> 1;
    const int lk0  = (tid & 1) * 8;

    float acc[8][8];
#pragma unroll
    for (int i = 0; i < 8; i++)
#pragma unroll
        for (int j = 0; j < 8; j++) acc[i][j] = 0.f;

    for (int k0 = 0; k0 < DM; k0 += 16) {
#pragma unroll
        for (int t = 0; t < 2; t++) {
            float4 a = *(const float4*)&g_o[(size_t)(m0 + lrow) * DM + k0 + lk0 + t * 4];
            int kk = lk0 + t * 4;
            As[kk + 0][lrow] = a.x; As[kk + 1][lrow] = a.y;
            As[kk + 2][lrow] = a.z; As[kk + 3][lrow] = a.w;
            float4 b = *(const float4*)&Wo[(size_t)(n0 + lrow) * DM + k0 + lk0 + t * 4];
            Bs[kk + 0][lrow] = b.x; Bs[kk + 1][lrow] = b.y;
            Bs[kk + 2][lrow] = b.z; Bs[kk + 3][lrow] = b.w;
        }
        __syncthreads();
#pragma unroll
        for (int kk = 0; kk < 16; kk++) {
            float4 a0 = *(const float4*)&As[kk][r];
            float4 a1 = *(const float4*)&As[kk][r + 64];
            float4 b0 = *(const float4*)&Bs[kk][c];
            float4 b1 = *(const float4*)&Bs[kk][c + 64];
            float av[8] = {a0.x, a0.y, a0.z, a0.w, a1.x, a1.y, a1.z, a1.w};
            float bw[8] = {b0.x, b0.y, b0.z, b0.w, b1.x, b1.y, b1.z, b1.w};
#pragma unroll
            for (int i = 0; i < 8; i++)
#pragma unroll
                for (int j = 0; j < 8; j++) acc[i][j] += av[i] * bw[j];
        }
        __syncthreads();
    }

#pragma unroll
    for (int i = 0; i < 8; i++) {
        int m = m0 + ((i < 4) ? (r + i) : (r + 64 + i - 4));
#pragma unroll
        for (int j = 0; j < 8; j++) {
            int n = n0 + ((j < 4) ? (c + j) : (c + 64 + j - 4));
            y[(size_t)m * DM + n] = acc[i][j] + bo[n];
        }
    }
}

// ---------------- launcher -------------------------------------------------
extern "C" void kernel_launch(void* const* d_in, const int* in_sizes, int n_in,
                              void* d_out, int out_size)
{
    const float* x  = (const float*)d_in[0];
    const float* Wq = (const float*)d_in[1];
    const float* bq = (const float*)d_in[2];
    const float* Wk = (const float*)d_in[3];
    const float* bk = (const float*)d_in[4];
    const float* Wv = (const float*)d_in[5];
    const float* bv = (const float*)d_in[6];
    const float* Wo = (const float*)d_in[7];
    const float* bo = (const float*)d_in[8];

    float* out = (float*)d_out;
    const size_t y_elems = (size_t)BB * NSEQ * DM;          // 4,194,304
    const size_t a_elems = (size_t)BB * NSEQ * NSEQ;        // 8,388,608
    const bool has_attn = (size_t)out_size >= y_elems + a_elems;
    float* attn_ptr = has_attn ? (out + y_elems) : g_o;     // fallback never used for output

    if (has_attn)
        zero_kernel<<<2048, 256>>>((float4*)attn_ptr, (int)(a_elems / 4));

    dim3 g1(DM / 128, (BB * NSEQ) / 128, 3);                // 8 x 32 x 3
    qkv_gemm<<<g1, 256>>>(x, Wq, bq, Wk, bk, Wv, bv);

    dim3 g2(136, BB * NH);                                  // triangular tiles x 32
    scores_gemm<<<g2, 256>>>();

    topk_attn<<<(BB * NH * NSEQ) / 8, 256>>>(attn_ptr);

    dim3 g3(DM / 128, (BB * NSEQ) / 128);                   // 8 x 32
    out_gemm<<<g3, 256>>>(Wo, bo, out);
}

// round 7
// speedup vs baseline: 1.2776x; 1.2776x over previous
#include <cuda_runtime.h>
#include <math.h>
#include <stdint.h>

#define BB 2
#define NSEQ 2048
#define NH 16
#define DH 64
#define DM 1024
#define KSEL 32

// ---------------- scratch (device globals; no cudaMalloc allowed) ----------
__device__ float g_q[(size_t)BB * NH * NSEQ * DH];     // 16.8 MB  [bh][n][d]
__device__ float g_k[(size_t)BB * NH * NSEQ * DH];     // 16.8 MB
__device__ float g_v[(size_t)BB * NH * NSEQ * DH];     // 16.8 MB
__device__ float g_o[(size_t)BB * NSEQ * DM];          // 16.8 MB  [b][n][h*64+d]
__device__ float g_s[(size_t)BB * NH * NSEQ * NSEQ];   // 536 MB   [bh][q][k]

// ---------------- warp helpers --------------------------------------------
__device__ __forceinline__ float warpSum(float v) {
#pragma unroll
    for (int o = 16; o; o >>= 1) v += __shfl_xor_sync(0xffffffffu, v, o);
    return v;
}

// full bitonic sort of 32 (value,index) across a warp, descending by value
__device__ __forceinline__ void bsort32_desc(float& v, int& i, int lane) {
#pragma unroll
    for (int k = 2; k <= 32; k <<= 1) {
#pragma unroll
        for (int j = k >> 1; j > 0; j >>= 1) {
            float ov = __shfl_xor_sync(0xffffffffu, v, j);
            int   oi = __shfl_xor_sync(0xffffffffu, i, j);
            bool up    = ((lane & k) != 0);   // flipped -> overall descending
            bool lower = ((lane & j) == 0);
            bool take  = (lower == up) ? (ov < v) : (ov > v);
            if (take) { v = ov; i = oi; }
        }
    }
}

// ---------------- zero fill ------------------------------------------------
__global__ void zero_kernel(float4* __restrict__ p, int n4) {
    int i = blockIdx.x * blockDim.x + threadIdx.x;
    int stride = gridDim.x * blockDim.x;
    float4 z = make_float4(0.f, 0.f, 0.f, 0.f);
    for (; i < n4; i += stride) p[i] = z;
}

// ---------------- QKV projection GEMM (x @ W^T + b), scatter per-head ------
__global__ __launch_bounds__(256) void qkv_gemm(
    const float* __restrict__ x,
    const float* __restrict__ Wq, const float* __restrict__ bq,
    const float* __restrict__ Wk, const float* __restrict__ bk,
    const float* __restrict__ Wv, const float* __restrict__ bv)
{
    const float* W; const float* bias; float* out;
    if (blockIdx.z == 0)      { W = Wq; bias = bq; out = g_q; }
    else if (blockIdx.z == 1) { W = Wk; bias = bk; out = g_k; }
    else                      { W = Wv; bias = bv; out = g_v; }

    __shared__ float As[16][132];
    __shared__ float Bs[16][132];

    const int tid = threadIdx.x;
    const int m0 = blockIdx.y * 128;
    const int n0 = blockIdx.x * 128;
    const int r  = (tid / 16) * 4;
    const int c  = (tid % 16) * 4;

    const int lrow = tid >> 1;               // 0..127
    const int lk0  = (tid & 1) * 8;          // 0 or 8

    float acc[8][8];
#pragma unroll
    for (int i = 0; i < 8; i++)
#pragma unroll
        for (int j = 0; j < 8; j++) acc[i][j] = 0.f;

    for (int k0 = 0; k0 < DM; k0 += 16) {
#pragma unroll
        for (int t = 0; t < 2; t++) {
            float4 a = *(const float4*)&x[(size_t)(m0 + lrow) * DM + k0 + lk0 + t * 4];
            int kk = lk0 + t * 4;
            As[kk + 0][lrow] = a.x; As[kk + 1][lrow] = a.y;
            As[kk + 2][lrow] = a.z; As[kk + 3][lrow] = a.w;
            float4 b = *(const float4*)&W[(size_t)(n0 + lrow) * DM + k0 + lk0 + t * 4];
            Bs[kk + 0][lrow] = b.x; Bs[kk + 1][lrow] = b.y;
            Bs[kk + 2][lrow] = b.z; Bs[kk + 3][lrow] = b.w;
        }
        __syncthreads();
#pragma unroll
        for (int kk = 0; kk < 16; kk++) {
            float4 a0 = *(const float4*)&As[kk][r];
            float4 a1 = *(const float4*)&As[kk][r + 64];
            float4 b0 = *(const float4*)&Bs[kk][c];
            float4 b1 = *(const float4*)&Bs[kk][c + 64];
            float av[8] = {a0.x, a0.y, a0.z, a0.w, a1.x, a1.y, a1.z, a1.w};
            float bw[8] = {b0.x, b0.y, b0.z, b0.w, b1.x, b1.y, b1.z, b1.w};
#pragma unroll
            for (int i = 0; i < 8; i++)
#pragma unroll
                for (int j = 0; j < 8; j++) acc[i][j] += av[i] * bw[j];
        }
        __syncthreads();
    }

#pragma unroll
    for (int i = 0; i < 8; i++) {
        int m = m0 + ((i < 4) ? (r + i) : (r + 64 + i - 4));
        int bIdx = m >> 11;
        int t = m & (NSEQ - 1);
#pragma unroll
        for (int j = 0; j < 8; j++) {
            int n = n0 + ((j < 4) ? (c + j) : (c + 64 + j - 4));
            int h = n >> 6;
            int d = n & 63;
            out[(((size_t)(bIdx * NH + h)) * NSEQ + t) * DH + d] = acc[i][j] + bias[n];
        }
    }
}

// ---------------- scores GEMM (lower-triangular tiles only) ----------------
__global__ __launch_bounds__(256) void scores_gemm()
{
    int bx = blockIdx.x;
    int qt = 0;
    while ((qt + 1) * (qt + 2) / 2 <= bx) qt++;
    int kt = bx - qt * (qt + 1) / 2;
    const int bh = blockIdx.y;

    const float* Qb = g_q + (size_t)bh * NSEQ * DH;
    const float* Kb = g_k + (size_t)bh * NSEQ * DH;
    float* Sb = g_s + (size_t)bh * NSEQ * NSEQ;

    __shared__ float As[16][132];
    __shared__ float Bs[16][132];

    const int tid = threadIdx.x;
    const int q0 = qt * 128;
    const int k0b = kt * 128;
    const int r = (tid / 16) * 4;
    const int c = (tid % 16) * 4;
    const int lrow = tid >> 1;
    const int lk0  = (tid & 1) * 8;

    float acc[8][8];
#pragma unroll
    for (int i = 0; i < 8; i++)
#pragma unroll
        for (int j = 0; j < 8; j++) acc[i][j] = 0.f;

    for (int k0 = 0; k0 < DH; k0 += 16) {
#pragma unroll
        for (int t = 0; t < 2; t++) {
            float4 a = *(const float4*)&Qb[(size_t)(q0 + lrow) * DH + k0 + lk0 + t * 4];
            int kk = lk0 + t * 4;
            As[kk + 0][lrow] = a.x; As[kk + 1][lrow] = a.y;
            As[kk + 2][lrow] = a.z; As[kk + 3][lrow] = a.w;
            float4 b = *(const float4*)&Kb[(size_t)(k0b + lrow) * DH + k0 + lk0 + t * 4];
            Bs[kk + 0][lrow] = b.x; Bs[kk + 1][lrow] = b.y;
            Bs[kk + 2][lrow] = b.z; Bs[kk + 3][lrow] = b.w;
        }
        __syncthreads();
#pragma unroll
        for (int kk = 0; kk < 16; kk++) {
            float4 a0 = *(const float4*)&As[kk][r];
            float4 a1 = *(const float4*)&As[kk][r + 64];
            float4 b0 = *(const float4*)&Bs[kk][c];
            float4 b1 = *(const float4*)&Bs[kk][c + 64];
            float av[8] = {a0.x, a0.y, a0.z, a0.w, a1.x, a1.y, a1.z, a1.w};
            float bw[8] = {b0.x, b0.y, b0.z, b0.w, b1.x, b1.y, b1.z, b1.w};
#pragma unroll
            for (int i = 0; i < 8; i++)
#pragma unroll
                for (int j = 0; j < 8; j++) acc[i][j] += av[i] * bw[j];
        }
        __syncthreads();
    }

#pragma unroll
    for (int i = 0; i < 8; i++) {
        int q = q0 + ((i < 4) ? (r + i) : (r + 64 + i - 4));
#pragma unroll
        for (int j = 0; j < 8; j++) {
            int k = k0b + ((j < 4) ? (c + j) : (c + 64 + j - 4));
            float val = (k <= q) ? acc[i][j] * 0.125f : -INFINITY;
            Sb[(size_t)q * NSEQ + k] = val;
        }
    }
}

// ---------------- streaming warp top-32 (candidate-insert) + softmax + AV --
// Per warp: maintain descending top-32 (value,index) list in registers.
// float4 loads (128 elems/chunk); per element-slot: 1 cmp + 1 ballot vs the
// running 32nd-largest; only record elements take the ~10-instr shift-insert.
// Stable inserts (strict >) reproduce top_k's lowest-index tie preference.
__global__ __launch_bounds__(256) void topk_attn(float* __restrict__ attn_out)
{
    const int wid = (blockIdx.x * blockDim.x + threadIdx.x) >> 5;
    const int lane = threadIdx.x & 31;
    const int rowid = wid & (NSEQ - 1);
    const int bh = wid >> 11;
    // balance: adjacent warps get (short, long) rows so blocks finish together
    const int q = (rowid & 1) ? (NSEQ - 1 - (rowid >> 1)) : (rowid >> 1);
    const int b = bh >> 4;
    const int h = bh & 15;

    const float* srow = g_s + ((size_t)bh * NSEQ + q) * NSEQ;
    const int nk = q + 1;

    float rv; int ri;
    float rmin;

    // ---- chunk 0: bulk-init list from first 32 strided values, then insert rest
    {
        float4 v4 = *(const float4*)(srow + lane * 4);
        rv = v4.x; ri = lane * 4;
        bsort32_desc(rv, ri, lane);
        rmin = __shfl_sync(0xffffffffu, rv, 31);
#pragma unroll
        for (int t = 1; t < 4; t++) {
            float v = (t == 1) ? v4.y : (t == 2) ? v4.z : v4.w;
            unsigned m = __ballot_sync(0xffffffffu, v > rmin);
            while (m) {
                int src = __ffs(m) - 1;
                m &= m - 1;
                float val = __shfl_sync(0xffffffffu, v, src);
                if (val > rmin) {
                    int nidx = src * 4 + t;
                    bool gt = val > rv;
                    float pv = __shfl_up_sync(0xffffffffu, rv, 1);
                    int   pi = __shfl_up_sync(0xffffffffu, ri, 1);
                    unsigned g = __ballot_sync(0xffffffffu, gt);
                    int pos = __ffs(g) - 1;
                    if (gt) {
                        rv = (lane == pos) ? val : pv;
                        ri = (lane == pos) ? nidx : pi;
                    }
                    rmin = __shfl_sync(0xffffffffu, rv, 31);
                }
            }
        }
    }

    // ---- remaining chunks (diag tile is fully written with -inf above q)
    for (int c0 = 128; c0 < nk; c0 += 128) {
        float4 v4 = *(const float4*)(srow + c0 + lane * 4);
#pragma unroll
        for (int t = 0; t < 4; t++) {
            float v = (t == 0) ? v4.x : (t == 1) ? v4.y : (t == 2) ? v4.z : v4.w;
            unsigned m = __ballot_sync(0xffffffffu, v > rmin);
            while (m) {
                int src = __ffs(m) - 1;
                m &= m - 1;
                float val = __shfl_sync(0xffffffffu, v, src);
                if (val > rmin) {                 // re-filter: rmin may have risen
                    int nidx = c0 + src * 4 + t;
                    bool gt = val > rv;
                    float pv = __shfl_up_sync(0xffffffffu, rv, 1);
                    int   pi = __shfl_up_sync(0xffffffffu, ri, 1);
                    unsigned g = __ballot_sync(0xffffffffu, gt);
                    int pos = __ffs(g) - 1;       // valid: val > rv[31]
                    if (gt) {
                        rv = (lane == pos) ? val : pv;
                        ri = (lane == pos) ? nidx : pi;
                    }
                    rmin = __shfl_sync(0xffffffffu, rv, 31);
                }
            }
        }
    }

    // softmax over kept 32 (rv=-inf entries contribute exactly 0)
    float mx = __shfl_sync(0xffffffffu, rv, 0);   // lane0 = max (finite: diag elem)
    float e = expf(rv - mx);                      // expf(-inf)=0
    float s = warpSum(e);
    float p = e / s;

    // out = sum_j p_j * V[idx_j]; lane covers dims {lane, lane+32}
    float acc0 = 0.f, acc1 = 0.f;
#pragma unroll 8
    for (int t = 0; t < 32; t++) {
        float pt = __shfl_sync(0xffffffffu, p, t);
        int   it = __shfl_sync(0xffffffffu, ri, t);
        if (pt > 0.f) {
            const float* vr = g_v + ((size_t)bh * NSEQ + it) * DH;
            acc0 += pt * vr[lane];
            acc1 += pt * vr[lane + 32];
        }
    }
    size_t obase = ((size_t)(b * NSEQ + q)) * DM + h * DH;
    g_o[obase + lane]      = acc0;
    g_o[obase + lane + 32] = acc1;

    // attn.mean over heads: scatter p/16 (exact zeros elsewhere)
    if (p > 0.f)
        atomicAdd(&attn_out[((size_t)b * NSEQ + q) * NSEQ + ri], p * (1.f / 16.f));
}

// ---------------- output projection: y = O @ Wo^T + bo ---------------------
__global__ __launch_bounds__(256) void out_gemm(
    const float* __restrict__ Wo, const float* __restrict__ bo,
    float* __restrict__ y)
{
    __shared__ float As[16][132];
    __shared__ float Bs[16][132];

    const int tid = threadIdx.x;
    const int m0 = blockIdx.y * 128;
    const int n0 = blockIdx.x * 128;
    const int r = (tid / 16) * 4;
    const int c = (tid % 16) * 4;
    const int lrow = tid >> 1;
    const int lk0  = (tid & 1) * 8;

    float acc[8][8];
#pragma unroll
    for (int i = 0; i < 8; i++)
#pragma unroll
        for (int j = 0; j < 8; j++) acc[i][j] = 0.f;

    for (int k0 = 0; k0 < DM; k0 += 16) {
#pragma unroll
        for (int t = 0; t < 2; t++) {
            float4 a = *(const float4*)&g_o[(size_t)(m0 + lrow) * DM + k0 + lk0 + t * 4];
            int kk = lk0 + t * 4;
            As[kk + 0][lrow] = a.x; As[kk + 1][lrow] = a.y;
            As[kk + 2][lrow] = a.z; As[kk + 3][lrow] = a.w;
            float4 b = *(const float4*)&Wo[(size_t)(n0 + lrow) * DM + k0 + lk0 + t * 4];
            Bs[kk + 0][lrow] = b.x; Bs[kk + 1][lrow] = b.y;
            Bs[kk + 2][lrow] = b.z; Bs[kk + 3][lrow] = b.w;
        }
        __syncthreads();
#pragma unroll
        for (int kk = 0; kk < 16; kk++) {
            float4 a0 = *(const float4*)&As[kk][r];
            float4 a1 = *(const float4*)&As[kk][r + 64];
            float4 b0 = *(const float4*)&Bs[kk][c];
            float4 b1 = *(const float4*)&Bs[kk][c + 64];
            float av[8] = {a0.x, a0.y, a0.z, a0.w, a1.x, a1.y, a1.z, a1.w};
            float bw[8] = {b0.x, b0.y, b0.z, b0.w, b1.x, b1.y, b1.z, b1.w};
#pragma unroll
            for (int i = 0; i < 8; i++)
#pragma unroll
                for (int j = 0; j < 8; j++) acc[i][j] += av[i] * bw[j];
        }
        __syncthreads();
    }

#pragma unroll
    for (int i = 0; i < 8; i++) {
        int m = m0 + ((i < 4) ? (r + i) : (r + 64 + i - 4));
#pragma unroll
        for (int j = 0; j < 8; j++) {
            int n = n0 + ((j < 4) ? (c + j) : (c + 64 + j - 4));
            y[(size_t)m * DM + n] = acc[i][j] + bo[n];
        }
    }
}

// ---------------- launcher -------------------------------------------------
extern "C" void kernel_launch(void* const* d_in, const int* in_sizes, int n_in,
                              void* d_out, int out_size)
{
    const float* x  = (const float*)d_in[0];
    const float* Wq = (const float*)d_in[1];
    const float* bq = (const float*)d_in[2];
    const float* Wk = (const float*)d_in[3];
    const float* bk = (const float*)d_in[4];
    const float* Wv = (const float*)d_in[5];
    const float* bv = (const float*)d_in[6];
    const float* Wo = (const float*)d_in[7];
    const float* bo = (const float*)d_in[8];

    float* out = (float*)d_out;
    const size_t y_elems = (size_t)BB * NSEQ * DM;          // 4,194,304
    const size_t a_elems = (size_t)BB * NSEQ * NSEQ;        // 8,388,608
    const bool has_attn = (size_t)out_size >= y_elems + a_elems;
    float* attn_ptr = has_attn ? (out + y_elems) : g_o;

    if (has_attn)
        zero_kernel<<<2048, 256>>>((float4*)attn_ptr, (int)(a_elems / 4));

    dim3 g1(DM / 128, (BB * NSEQ) / 128, 3);                // 8 x 32 x 3
    qkv_gemm<<<g1, 256>>>(x, Wq, bq, Wk, bk, Wv, bv);

    dim3 g2(136, BB * NH);                                  // triangular tiles x 32
    scores_gemm<<<g2, 256>>>();

    topk_attn<<<(BB * NH * NSEQ) / 8, 256>>>(attn_ptr);

    dim3 g3(DM / 128, (BB * NSEQ) / 128);                   // 8 x 32
    out_gemm<<<g3, 256>>>(Wo, bo, out);
}

// round 11
// speedup vs baseline: 1.3487x; 1.0557x over previous
#include <cuda_runtime.h>
#include <cuda_bf16.h>
#include <math.h>
#include <stdint.h>

#define BB 2
#define NSEQ 2048
#define NH 16
#define DH 64
#define DM 1024

// ---------------- scratch (device globals; no cudaMalloc allowed) ----------
__device__ float g_q[(size_t)BB * NH * NSEQ * DH];     // fp32 [bh][n][d]
__device__ float g_k[(size_t)BB * NH * NSEQ * DH];
__device__ float g_v[(size_t)BB * NH * NSEQ * DH];
__device__ float g_s[(size_t)BB * NH * NSEQ * NSEQ];   // 536 MB [bh][q][k]
// O and Wo as 3-way bf16 split (hi/mid/lo ~ fp32) for the HMMA output GEMM
__device__ __align__(16) __nv_bfloat16 g_oh[(size_t)BB * NSEQ * DM];
__device__ __align__(16) __nv_bfloat16 g_om[(size_t)BB * NSEQ * DM];
__device__ __align__(16) __nv_bfloat16 g_ol[(size_t)BB * NSEQ * DM];
__device__ __align__(16) __nv_bfloat16 g_wh[(size_t)DM * DM];
__device__ __align__(16) __nv_bfloat16 g_wm[(size_t)DM * DM];
__device__ __align__(16) __nv_bfloat16 g_wl[(size_t)DM * DM];

// stage layout: Ah@0 Am@16K Al@32K Bh@48K Bm@64K Bl@80K ; stage = 96KB
#define RG 16384
#define STG 98304

// ==================== small helpers ========================================
__device__ __forceinline__ uint32_t smem_u32(const void* p) {
    uint32_t a;
    asm("{ .reg .u64 t; cvta.to.shared.u64 t, %1; cvt.u32.u64 %0, t; }"
        : "=r"(a) : "l"(p));
    return a;
}
__device__ __forceinline__ void cp16(uint32_t dst, const void* src) {
    asm volatile("cp.async.cg.shared.global [%0], [%1], 16;"
                 :: "r"(dst), "l"(src) : "memory");
}
#define CP_COMMIT() asm volatile("cp.async.commit_group;" ::: "memory")
#define CP_WAIT0()  asm volatile("cp.async.wait_group 0;" ::: "memory")
#define CP_WAIT1()  asm volatile("cp.async.wait_group 1;" ::: "memory")

__device__ __forceinline__ void mma16816(float* d, const uint32_t* a,
                                         uint32_t b0, uint32_t b1) {
    asm volatile(
        "mma.sync.aligned.m16n8k16.row.col.f32.bf16.bf16.f32 "
        "{%0,%1,%2,%3}, {%4,%5,%6,%7}, {%8,%9}, {%0,%1,%2,%3};"
        : "+f"(d[0]), "+f"(d[1]), "+f"(d[2]), "+f"(d[3])
        : "r"(a[0]), "r"(a[1]), "r"(a[2]), "r"(a[3]), "r"(b0), "r"(b1));
}
__device__ __forceinline__ uint32_t ldsw(const char* region, int off) {
    return *(const uint32_t*)(region + (off ^ ((off >> 3) & 0x70)));
}
__device__ __forceinline__ void split3(float a, float b, uint32_t& ph,
                                       uint32_t& pm, uint32_t& pl) {
    __nv_bfloat162 h = __floats2bfloat162_rn(a, b);
    float ra = a - __bfloat162float(h.x);
    float rb = b - __bfloat162float(h.y);
    __nv_bfloat162 m = __floats2bfloat162_rn(ra, rb);
    ra -= __bfloat162float(m.x);
    rb -= __bfloat162float(m.y);
    __nv_bfloat162 l = __floats2bfloat162_rn(ra, rb);
    ph = *(uint32_t*)&h; pm = *(uint32_t*)&m; pl = *(uint32_t*)&l;
}

// ========== copy one K=64 chunk of A,B (h/m/l) into a 96KB smem stage ======
__device__ __forceinline__ void stage_copy(
    const __nv_bfloat16* __restrict__ Ah, const __nv_bfloat16* __restrict__ Am,
    const __nv_bfloat16* __restrict__ Al, int lda,
    const __nv_bfloat16* __restrict__ Bh, const __nv_bfloat16* __restrict__ Bm,
    const __nv_bfloat16* __restrict__ Bl, int ldb,
    int kc, uint32_t sbase, int tid)
{
#pragma unroll
    for (int i = 0; i < 4; i++) {
        int u = tid + i * 256;
        int row = u >> 3;
        int cb = (u & 7) * 16;
        int off = row * 128 + cb;
        int sw = off ^ ((off >> 3) & 0x70);
        size_t ao = (size_t)row * lda + kc;
        size_t bo = (size_t)row * ldb + kc;
        cp16(sbase + 0 * RG + sw, (const char*)(Ah + ao) + cb);
        cp16(sbase + 1 * RG + sw, (const char*)(Am + ao) + cb);
        cp16(sbase + 2 * RG + sw, (const char*)(Al + ao) + cb);
        cp16(sbase + 3 * RG + sw, (const char*)(Bh + bo) + cb);
        cp16(sbase + 4 * RG + sw, (const char*)(Bm + bo) + cb);
        cp16(sbase + 5 * RG + sw, (const char*)(Bl + bo) + cb);
    }
}

// ========== compute one K=64 chunk: acc += A(128x64) * B(128x64)^T =========
__device__ __forceinline__ void compute_chunk(
    const char* st, int lane, int wm, int wn, float acc[2][8][4])
{
    const int g = lane >> 2, tig = lane & 3;
    const char* Ah = st;
    const char* Am = st + 1 * RG;
    const char* Al = st + 2 * RG;
    const char* Bh = st + 3 * RG;
    const char* Bm = st + 4 * RG;
    const char* Bl = st + 5 * RG;
#pragma unroll
    for (int ks = 0; ks < 4; ks++) {
        const int kb = ks * 32 + tig * 4;
        uint32_t ah[2][4], am[2][4], al[2][4];
#pragma unroll
        for (int mf = 0; mf < 2; mf++) {
            int r = (wm * 32 + mf * 16 + g) * 128;
            ah[mf][0] = ldsw(Ah, r + kb);
            ah[mf][1] = ldsw(Ah, r + 1024 + kb);
            ah[mf][2] = ldsw(Ah, r + kb + 16);
            ah[mf][3] = ldsw(Ah, r + 1024 + kb + 16);
            am[mf][0] = ldsw(Am, r + kb);
            am[mf][1] = ldsw(Am, r + 1024 + kb);
            am[mf][2] = ldsw(Am, r + kb + 16);
            am[mf][3] = ldsw(Am, r + 1024 + kb + 16);
            al[mf][0] = ldsw(Al, r + kb);
            al[mf][1] = ldsw(Al, r + 1024 + kb);
            al[mf][2] = ldsw(Al, r + kb + 16);
            al[mf][3] = ldsw(Al, r + 1024 + kb + 16);
        }
#pragma unroll
        for (int nf = 0; nf < 8; nf++) {
            int rn = (wn * 64 + nf * 8 + g) * 128;
            uint32_t bh0 = ldsw(Bh, rn + kb), bh1 = ldsw(Bh, rn + kb + 16);
            uint32_t bm0 = ldsw(Bm, rn + kb), bm1 = ldsw(Bm, rn + kb + 16);
            uint32_t bl0 = ldsw(Bl, rn + kb), bl1 = ldsw(Bl, rn + kb + 16);
#pragma unroll
            for (int mf = 0; mf < 2; mf++) {
                mma16816(acc[mf][nf], al[mf], bh0, bh1);   // lh
                mma16816(acc[mf][nf], ah[mf], bl0, bl1);   // hl
                mma16816(acc[mf][nf], am[mf], bm0, bm1);   // mm
                mma16816(acc[mf][nf], am[mf], bh0, bh1);   // mh
                mma16816(acc[mf][nf], ah[mf], bm0, bm1);   // hm
                mma16816(acc[mf][nf], ah[mf], bh0, bh1);   // hh
            }
        }
    }
}

__device__ __forceinline__ void hgemm_mainloop(
    const __nv_bfloat16* Ah, const __nv_bfloat16* Am, const __nv_bfloat16* Al, int lda,
    const __nv_bfloat16* Bh, const __nv_bfloat16* Bm, const __nv_bfloat16* Bl, int ldb,
    int nchunk, char* tiles, int tid, float acc[2][8][4])
{
    const int lane = tid & 31, wid = tid >> 5, wm = wid & 3, wn = wid >> 2;
#pragma unroll
    for (int i = 0; i < 2; i++)
#pragma unroll
        for (int j = 0; j < 8; j++)
#pragma unroll
            for (int r = 0; r < 4; r++) acc[i][j][r] = 0.f;

    uint32_t sb = smem_u32(tiles);
    stage_copy(Ah, Am, Al, lda, Bh, Bm, Bl, ldb, 0, sb, tid);
    CP_COMMIT();
    for (int c = 0; c < nchunk; c++) {
        if (c + 1 < nchunk) {
            stage_copy(Ah, Am, Al, lda, Bh, Bm, Bl, ldb, (c + 1) * 64,
                       sb + ((c + 1) & 1) * STG, tid);
            CP_COMMIT();
            CP_WAIT1();
        } else {
            CP_WAIT0();
        }
        __syncthreads();
        compute_chunk(tiles + (c & 1) * STG, lane, wm, wn, acc);
        __syncthreads();
    }
}

// ==================== convert Wo to bf16 h/m/l =============================
__global__ __launch_bounds__(256) void convert_wo(const float* __restrict__ Wo)
{
    const int total = (DM * DM) / 4;
    for (int idx = blockIdx.x * blockDim.x + threadIdx.x; idx < total;
         idx += gridDim.x * blockDim.x) {
        float4 f = *(const float4*)(Wo + (size_t)idx * 4);
        uint2 ph, pm, pl;
        split3(f.x, f.y, ph.x, pm.x, pl.x);
        split3(f.z, f.w, ph.y, pm.y, pl.y);
        *(uint2*)(g_wh + (size_t)idx * 4) = ph;
        *(uint2*)(g_wm + (size_t)idx * 4) = pm;
        *(uint2*)(g_wl + (size_t)idx * 4) = pl;
    }
}

// ==================== output projection y = O Wo^T + bo (HMMA) =============
__global__ __launch_bounds__(256) void mma_out(
    const float* __restrict__ bo, float* __restrict__ y)
{
    extern __shared__ char smraw[];
    const uint32_t smb = smem_u32(smraw);
    char* tiles = smraw + (((smb + 1023) & ~1023u) - smb);
    const int tid = threadIdx.x, lane = tid & 31, wid = tid >> 5;
    const int g = lane >> 2, tig = lane & 3;
    const int wm = wid & 3, wn = wid >> 2;
    const int n0 = blockIdx.x * 128, m0 = blockIdx.y * 128;

    float acc[2][8][4];
    hgemm_mainloop(g_oh + (size_t)m0 * DM, g_om + (size_t)m0 * DM,
                   g_ol + (size_t)m0 * DM, DM,
                   g_wh + (size_t)n0 * DM, g_wm + (size_t)n0 * DM,
                   g_wl + (size_t)n0 * DM, DM,
                   16, tiles, tid, acc);

#pragma unroll
    for (int mf = 0; mf < 2; mf++)
#pragma unroll
        for (int nf = 0; nf < 8; nf++) {
            int n = n0 + wn * 64 + nf * 8 + tig * 2;
            float b0v = __ldg(&bo[n]), b1v = __ldg(&bo[n + 1]);
#pragma unroll
            for (int part = 0; part < 2; part++) {
                int m = m0 + wm * 32 + mf * 16 + g + part * 8;
                *(float2*)(y + (size_t)m * DM + n) =
                    make_float2(acc[mf][nf][part * 2 + 0] + b0v,
                                acc[mf][nf][part * 2 + 1] + b1v);
            }
        }
}

// ==================== zero fill ============================================
__global__ void zero_kernel(float4* __restrict__ p, int n4) {
    int i = blockIdx.x * blockDim.x + threadIdx.x;
    int stride = gridDim.x * blockDim.x;
    float4 z = make_float4(0.f, 0.f, 0.f, 0.f);
    for (; i < n4; i += stride) p[i] = z;
}

// ==================== QKV projection GEMM (FFMA, known-good R7) ============
__global__ __launch_bounds__(256) void qkv_gemm(
    const float* __restrict__ x,
    const float* __restrict__ Wq, const float* __restrict__ bq,
    const float* __restrict__ Wk, const float* __restrict__ bk,
    const float* __restrict__ Wv, const float* __restrict__ bv)
{
    const float* W; const float* bias; float* out;
    if (blockIdx.z == 0)      { W = Wq; bias = bq; out = g_q; }
    else if (blockIdx.z == 1) { W = Wk; bias = bk; out = g_k; }
    else                      { W = Wv; bias = bv; out = g_v; }

    __shared__ float As[16][132];
    __shared__ float Bs[16][132];

    const int tid = threadIdx.x;
    const int m0 = blockIdx.y * 128;
    const int n0 = blockIdx.x * 128;
    const int r  = (tid / 16) * 4;
    const int c  = (tid % 16) * 4;
    const int lrow = tid >> 1;
    const int lk0  = (tid & 1) * 8;

    float acc[8][8];
#pragma unroll
    for (int i = 0; i < 8; i++)
#pragma unroll
        for (int j = 0; j < 8; j++) acc[i][j] = 0.f;

    for (int k0 = 0; k0 < DM; k0 += 16) {
#pragma unroll
        for (int t = 0; t < 2; t++) {
            float4 a = *(const float4*)&x[(size_t)(m0 + lrow) * DM + k0 + lk0 + t * 4];
            int kk = lk0 + t * 4;
            As[kk + 0][lrow] = a.x; As[kk + 1][lrow] = a.y;
            As[kk + 2][lrow] = a.z; As[kk + 3][lrow] = a.w;
            float4 b = *(const float4*)&W[(size_t)(n0 + lrow) * DM + k0 + lk0 + t * 4];
            Bs[kk + 0][lrow] = b.x; Bs[kk + 1][lrow] = b.y;
            Bs[kk + 2][lrow] = b.z; Bs[kk + 3][lrow] = b.w;
        }
        __syncthreads();
#pragma unroll
        for (int kk = 0; kk < 16; kk++) {
            float4 a0 = *(const float4*)&As[kk][r];
            float4 a1 = *(const float4*)&As[kk][r + 64];
            float4 b0 = *(const float4*)&Bs[kk][c];
            float4 b1 = *(const float4*)&Bs[kk][c + 64];
            float av[8] = {a0.x, a0.y, a0.z, a0.w, a1.x, a1.y, a1.z, a1.w};
            float bw[8] = {b0.x, b0.y, b0.z, b0.w, b1.x, b1.y, b1.z, b1.w};
#pragma unroll
            for (int i = 0; i < 8; i++)
#pragma unroll
                for (int j = 0; j < 8; j++) acc[i][j] += av[i] * bw[j];
        }
        __syncthreads();
    }

#pragma unroll
    for (int i = 0; i < 8; i++) {
        int m = m0 + ((i < 4) ? (r + i) : (r + 64 + i - 4));
        int bIdx = m >> 11;
        int t = m & (NSEQ - 1);
#pragma unroll
        for (int j = 0; j < 8; j++) {
            int n = n0 + ((j < 4) ? (c + j) : (c + 64 + j - 4));
            int h = n >> 6;
            int d = n & 63;
            out[(((size_t)(bIdx * NH + h)) * NSEQ + t) * DH + d] = acc[i][j] + bias[n];
        }
    }
}

// ==================== scores GEMM (FFMA, known-good R7) ====================
__global__ __launch_bounds__(256) void scores_gemm()
{
    int bx = blockIdx.x;
    int qt = 0;
    while ((qt + 1) * (qt + 2) / 2 <= bx) qt++;
    int kt = bx - qt * (qt + 1) / 2;
    const int bh = blockIdx.y;

    const float* Qb = g_q + (size_t)bh * NSEQ * DH;
    const float* Kb = g_k + (size_t)bh * NSEQ * DH;
    float* Sb = g_s + (size_t)bh * NSEQ * NSEQ;

    __shared__ float As[16][132];
    __shared__ float Bs[16][132];

    const int tid = threadIdx.x;
    const int q0 = qt * 128;
    const int k0b = kt * 128;
    const int r = (tid / 16) * 4;
    const int c = (tid % 16) * 4;
    const int lrow = tid >> 1;
    const int lk0  = (tid & 1) * 8;

    float acc[8][8];
#pragma unroll
    for (int i = 0; i < 8; i++)
#pragma unroll
        for (int j = 0; j < 8; j++) acc[i][j] = 0.f;

    for (int k0 = 0; k0 < DH; k0 += 16) {
#pragma unroll
        for (int t = 0; t < 2; t++) {
            float4 a = *(const float4*)&Qb[(size_t)(q0 + lrow) * DH + k0 + lk0 + t * 4];
            int kk = lk0 + t * 4;
            As[kk + 0][lrow] = a.x; As[kk + 1][lrow] = a.y;
            As[kk + 2][lrow] = a.z; As[kk + 3][lrow] = a.w;
            float4 b = *(const float4*)&Kb[(size_t)(k0b + lrow) * DH + k0 + lk0 + t * 4];
            Bs[kk + 0][lrow] = b.x; Bs[kk + 1][lrow] = b.y;
            Bs[kk + 2][lrow] = b.z; Bs[kk + 3][lrow] = b.w;
        }
        __syncthreads();
#pragma unroll
        for (int kk = 0; kk < 16; kk++) {
            float4 a0 = *(const float4*)&As[kk][r];
            float4 a1 = *(const float4*)&As[kk][r + 64];
            float4 b0 = *(const float4*)&Bs[kk][c];
            float4 b1 = *(const float4*)&Bs[kk][c + 64];
            float av[8] = {a0.x, a0.y, a0.z, a0.w, a1.x, a1.y, a1.z, a1.w};
            float bw[8] = {b0.x, b0.y, b0.z, b0.w, b1.x, b1.y, b1.z, b1.w};
#pragma unroll
            for (int i = 0; i < 8; i++)
#pragma unroll
                for (int j = 0; j < 8; j++) acc[i][j] += av[i] * bw[j];
        }
        __syncthreads();
    }

#pragma unroll
    for (int i = 0; i < 8; i++) {
        int q = q0 + ((i < 4) ? (r + i) : (r + 64 + i - 4));
#pragma unroll
        for (int j = 0; j < 8; j++) {
            int k = k0b + ((j < 4) ? (c + j) : (c + 64 + j - 4));
            float val = (k <= q) ? acc[i][j] * 0.125f : -INFINITY;
            Sb[(size_t)q * NSEQ + k] = val;
        }
    }
}

// ==================== topk helpers =========================================
__device__ __forceinline__ float warpSum(float v) {
#pragma unroll
    for (int o = 16; o; o >>= 1) v += __shfl_xor_sync(0xffffffffu, v, o);
    return v;
}
__device__ __forceinline__ void bsort32_desc(float& v, int& i, int lane) {
#pragma unroll
    for (int k = 2; k <= 32; k <<= 1) {
#pragma unroll
        for (int j = k >> 1; j > 0; j >>= 1) {
            float ov = __shfl_xor_sync(0xffffffffu, v, j);
            int   oi = __shfl_xor_sync(0xffffffffu, i, j);
            bool up    = ((lane & k) != 0);
            bool lower = ((lane & j) == 0);
            bool take  = (lower == up) ? (ov < v) : (ov > v);
            if (take) { v = ov; i = oi; }
        }
    }
}

// ==================== streaming warp top-32 + softmax + AV =================
__global__ __launch_bounds__(256) void topk_attn(float* __restrict__ attn_out)
{
    const int wid = (blockIdx.x * blockDim.x + threadIdx.x) >> 5;
    const int lane = threadIdx.x & 31;
    const int rowid = wid & (NSEQ - 1);
    const int bh = wid >> 11;
    const int q = (rowid & 1) ? (NSEQ - 1 - (rowid >> 1)) : (rowid >> 1);
    const int b = bh >> 4;
    const int h = bh & 15;

    const float* srow = g_s + ((size_t)bh * NSEQ + q) * NSEQ;
    const int nk = q + 1;

    float rv; int ri;
    float rmin;

    {
        float4 v4 = *(const float4*)(srow + lane * 4);
        rv = v4.x; ri = lane * 4;
        bsort32_desc(rv, ri, lane);
        rmin = __shfl_sync(0xffffffffu, rv, 31);
#pragma unroll
        for (int t = 1; t < 4; t++) {
            float v = (t == 1) ? v4.y : (t == 2) ? v4.z : v4.w;
            unsigned m = __ballot_sync(0xffffffffu, v > rmin);
            while (m) {
                int src = __ffs(m) - 1;
                m &= m - 1;
                float val = __shfl_sync(0xffffffffu, v, src);
                if (val > rmin) {
                    int nidx = src * 4 + t;
                    bool gt = val > rv;
                    float pv = __shfl_up_sync(0xffffffffu, rv, 1);
                    int   pi = __shfl_up_sync(0xffffffffu, ri, 1);
                    unsigned gmask = __ballot_sync(0xffffffffu, gt);
                    int pos = __ffs(gmask) - 1;
                    if (gt) {
                        rv = (lane == pos) ? val : pv;
                        ri = (lane == pos) ? nidx : pi;
                    }
                    rmin = __shfl_sync(0xffffffffu, rv, 31);
                }
            }
        }
    }

    for (int c0 = 128; c0 < nk; c0 += 128) {
        float4 v4 = *(const float4*)(srow + c0 + lane * 4);
#pragma unroll
        for (int t = 0; t < 4; t++) {
            float v = (t == 0) ? v4.x : (t == 1) ? v4.y : (t == 2) ? v4.z : v4.w;
            unsigned m = __ballot_sync(0xffffffffu, v > rmin);
            while (m) {
                int src = __ffs(m) - 1;
                m &= m - 1;
                float val = __shfl_sync(0xffffffffu, v, src);
                if (val > rmin) {
                    int nidx = c0 + src * 4 + t;
                    bool gt = val > rv;
                    float pv = __shfl_up_sync(0xffffffffu, rv, 1);
                    int   pi = __shfl_up_sync(0xffffffffu, ri, 1);
                    unsigned gmask = __ballot_sync(0xffffffffu, gt);
                    int pos = __ffs(gmask) - 1;
                    if (gt) {
                        rv = (lane == pos) ? val : pv;
                        ri = (lane == pos) ? nidx : pi;
                    }
                    rmin = __shfl_sync(0xffffffffu, rv, 31);
                }
            }
        }
    }

    float mx = __shfl_sync(0xffffffffu, rv, 0);
    float e = expf(rv - mx);
    float s = warpSum(e);
    float p = e / s;

    float acc0 = 0.f, acc1 = 0.f;
#pragma unroll 8
    for (int t = 0; t < 32; t++) {
        float pt = __shfl_sync(0xffffffffu, p, t);
        int   it = __shfl_sync(0xffffffffu, ri, t);
        if (pt > 0.f) {
            const float* vr = g_v + ((size_t)bh * NSEQ + it) * DH;
            acc0 += pt * vr[lane];
            acc1 += pt * vr[lane + 32];
        }
    }
    // O written as bf16 h/m/l (exact 24-bit split of the fp32 value)
    size_t obase = ((size_t)(b * NSEQ + q)) * DM + h * DH;
    {
        __nv_bfloat16 h0 = __float2bfloat16(acc0);
        float r0 = acc0 - __bfloat162float(h0);
        __nv_bfloat16 m0v = __float2bfloat16(r0);
        __nv_bfloat16 l0 = __float2bfloat16(r0 - __bfloat162float(m0v));
        g_oh[obase + lane] = h0; g_om[obase + lane] = m0v; g_ol[obase + lane] = l0;
        __nv_bfloat16 h1 = __float2bfloat16(acc1);
        float r1 = acc1 - __bfloat162float(h1);
        __nv_bfloat16 m1v = __float2bfloat16(r1);
        __nv_bfloat16 l1 = __float2bfloat16(r1 - __bfloat162float(m1v));
        g_oh[obase + lane + 32] = h1; g_om[obase + lane + 32] = m1v;
        g_ol[obase + lane + 32] = l1;
    }

    if (p > 0.f)
        atomicAdd(&attn_out[((size_t)b * NSEQ + q) * NSEQ + ri], p * (1.f / 16.f));
}

// ==================== launcher =============================================
extern "C" void kernel_launch(void* const* d_in, const int* in_sizes, int n_in,
                              void* d_out, int out_size)
{
    const float* x  = (const float*)d_in[0];
    const float* Wq = (const float*)d_in[1];
    const float* bq = (const float*)d_in[2];
    const float* Wk = (const float*)d_in[3];
    const float* bk = (const float*)d_in[4];
    const float* Wv = (const float*)d_in[5];
    const float* bv = (const float*)d_in[6];
    const float* Wo = (const float*)d_in[7];
    const float* bo = (const float*)d_in[8];

    float* out = (float*)d_out;
    const size_t y_elems = (size_t)BB * NSEQ * DM;
    const size_t a_elems = (size_t)BB * NSEQ * NSEQ;
    const bool has_attn = (size_t)out_size >= y_elems + a_elems;
    float* attn_ptr = has_attn ? (out + y_elems) : g_s;

    const int SM_2ST = 1024 + 2 * STG;
    cudaFuncSetAttribute(mma_out, cudaFuncAttributeMaxDynamicSharedMemorySize, SM_2ST);

    if (has_attn)
        zero_kernel<<<2048, 256>>>((float4*)attn_ptr, (int)(a_elems / 4));

    convert_wo<<<512, 256>>>(Wo);

    dim3 g1(DM / 128, (BB * NSEQ) / 128, 3);
    qkv_gemm<<<g1, 256>>>(x, Wq, bq, Wk, bk, Wv, bv);

    dim3 g2(136, BB * NH);
    scores_gemm<<<g2, 256>>>();

    topk_attn<<<(BB * NH * NSEQ) / 8, 256>>>(attn_ptr);

    dim3 g3(DM / 128, (BB * NSEQ) / 128);
    mma_out<<<g3, 256, SM_2ST>>>(bo, out);
}

// round 15
// speedup vs baseline: 1.3810x; 1.0240x over previous
#include <cuda_runtime.h>
#include <cuda_bf16.h>
#include <math.h>
#include <stdint.h>

#define BB 2
#define NSEQ 2048
#define NH 16
#define DH 64
#define DM 1024

// ---------------- scratch (device globals; no cudaMalloc allowed) ----------
__device__ float g_q[(size_t)BB * NH * NSEQ * DH];     // fp32 [bh][n][d]
__device__ float g_k[(size_t)BB * NH * NSEQ * DH];
__device__ float g_v[(size_t)BB * NH * NSEQ * DH];
__device__ float g_s[(size_t)BB * NH * NSEQ * NSEQ];   // 536 MB [bh][q][k]
// 3-way bf16 splits for HMMA GEMMs (V projection + output projection only)
__device__ __align__(16) __nv_bfloat16 g_xh[(size_t)BB * NSEQ * DM];
__device__ __align__(16) __nv_bfloat16 g_xm[(size_t)BB * NSEQ * DM];
__device__ __align__(16) __nv_bfloat16 g_xl[(size_t)BB * NSEQ * DM];
__device__ __align__(16) __nv_bfloat16 g_wh[(size_t)2 * DM * DM];   // Wv, Wo
__device__ __align__(16) __nv_bfloat16 g_wm[(size_t)2 * DM * DM];
__device__ __align__(16) __nv_bfloat16 g_wl[(size_t)2 * DM * DM];
__device__ __align__(16) __nv_bfloat16 g_oh[(size_t)BB * NSEQ * DM];
__device__ __align__(16) __nv_bfloat16 g_om[(size_t)BB * NSEQ * DM];
__device__ __align__(16) __nv_bfloat16 g_ol[(size_t)BB * NSEQ * DM];

// stage layout: Ah@0 Am@16K Al@32K Bh@48K Bm@64K Bl@80K ; stage = 96KB
#define RG 16384
#define STG 98304

// ==================== small helpers ========================================
__device__ __forceinline__ uint32_t smem_u32(const void* p) {
    uint32_t a;
    asm("{ .reg .u64 t; cvta.to.shared.u64 t, %1; cvt.u32.u64 %0, t; }"
        : "=r"(a) : "l"(p));
    return a;
}
__device__ __forceinline__ void cp16(uint32_t dst, const void* src) {
    asm volatile("cp.async.cg.shared.global [%0], [%1], 16;"
                 :: "r"(dst), "l"(src) : "memory");
}
#define CP_COMMIT() asm volatile("cp.async.commit_group;" ::: "memory")
#define CP_WAIT0()  asm volatile("cp.async.wait_group 0;" ::: "memory")
#define CP_WAIT1()  asm volatile("cp.async.wait_group 1;" ::: "memory")

__device__ __forceinline__ void mma16816(float* d, const uint32_t* a,
                                         uint32_t b0, uint32_t b1) {
    asm volatile(
        "mma.sync.aligned.m16n8k16.row.col.f32.bf16.bf16.f32 "
        "{%0,%1,%2,%3}, {%4,%5,%6,%7}, {%8,%9}, {%0,%1,%2,%3};"
        : "+f"(d[0]), "+f"(d[1]), "+f"(d[2]), "+f"(d[3])
        : "r"(a[0]), "r"(a[1]), "r"(a[2]), "r"(a[3]), "r"(b0), "r"(b1));
}
__device__ __forceinline__ uint32_t ldsw(const char* region, int off) {
    return *(const uint32_t*)(region + (off ^ ((off >> 3) & 0x70)));
}
__device__ __forceinline__ void split3(float a, float b, uint32_t& ph,
                                       uint32_t& pm, uint32_t& pl) {
    __nv_bfloat162 h = __floats2bfloat162_rn(a, b);
    float ra = a - __bfloat162float(h.x);
    float rb = b - __bfloat162float(h.y);
    __nv_bfloat162 m = __floats2bfloat162_rn(ra, rb);
    ra -= __bfloat162float(m.x);
    rb -= __bfloat162float(m.y);
    __nv_bfloat162 l = __floats2bfloat162_rn(ra, rb);
    ph = *(uint32_t*)&h; pm = *(uint32_t*)&m; pl = *(uint32_t*)&l;
}

// ========== copy one K=64 chunk of A,B (h/m/l) into a 96KB smem stage ======
__device__ __forceinline__ void stage_copy(
    const __nv_bfloat16* __restrict__ Ah, const __nv_bfloat16* __restrict__ Am,
    const __nv_bfloat16* __restrict__ Al, int lda,
    const __nv_bfloat16* __restrict__ Bh, const __nv_bfloat16* __restrict__ Bm,
    const __nv_bfloat16* __restrict__ Bl, int ldb,
    int kc, uint32_t sbase, int tid)
{
#pragma unroll
    for (int i = 0; i < 4; i++) {
        int u = tid + i * 256;
        int row = u >> 3;
        int cb = (u & 7) * 16;
        int off = row * 128 + cb;
        int sw = off ^ ((off >> 3) & 0x70);
        size_t ao = (size_t)row * lda + kc;
        size_t bo = (size_t)row * ldb + kc;
        cp16(sbase + 0 * RG + sw, (const char*)(Ah + ao) + cb);
        cp16(sbase + 1 * RG + sw, (const char*)(Am + ao) + cb);
        cp16(sbase + 2 * RG + sw, (const char*)(Al + ao) + cb);
        cp16(sbase + 3 * RG + sw, (const char*)(Bh + bo) + cb);
        cp16(sbase + 4 * RG + sw, (const char*)(Bm + bo) + cb);
        cp16(sbase + 5 * RG + sw, (const char*)(Bl + bo) + cb);
    }
}

// ========== compute one K=64 chunk: acc += A(128x64) * B(128x64)^T =========
__device__ __forceinline__ void compute_chunk(
    const char* st, int lane, int wm, int wn, float acc[2][8][4])
{
    const int g = lane >> 2, tig = lane & 3;
    const char* Ah = st;
    const char* Am = st + 1 * RG;
    const char* Al = st + 2 * RG;
    const char* Bh = st + 3 * RG;
    const char* Bm = st + 4 * RG;
    const char* Bl = st + 5 * RG;
#pragma unroll
    for (int ks = 0; ks < 4; ks++) {
        const int kb = ks * 32 + tig * 4;
        uint32_t ah[2][4], am[2][4], al[2][4];
#pragma unroll
        for (int mf = 0; mf < 2; mf++) {
            int r = (wm * 32 + mf * 16 + g) * 128;
            ah[mf][0] = ldsw(Ah, r + kb);
            ah[mf][1] = ldsw(Ah, r + 1024 + kb);
            ah[mf][2] = ldsw(Ah, r + kb + 16);
            ah[mf][3] = ldsw(Ah, r + 1024 + kb + 16);
            am[mf][0] = ldsw(Am, r + kb);
            am[mf][1] = ldsw(Am, r + 1024 + kb);
            am[mf][2] = ldsw(Am, r + kb + 16);
            am[mf][3] = ldsw(Am, r + 1024 + kb + 16);
            al[mf][0] = ldsw(Al, r + kb);
            al[mf][1] = ldsw(Al, r + 1024 + kb);
            al[mf][2] = ldsw(Al, r + kb + 16);
            al[mf][3] = ldsw(Al, r + 1024 + kb + 16);
        }
#pragma unroll
        for (int nf = 0; nf < 8; nf++) {
            int rn = (wn * 64 + nf * 8 + g) * 128;
            uint32_t bh0 = ldsw(Bh, rn + kb), bh1 = ldsw(Bh, rn + kb + 16);
            uint32_t bm0 = ldsw(Bm, rn + kb), bm1 = ldsw(Bm, rn + kb + 16);
            uint32_t bl0 = ldsw(Bl, rn + kb), bl1 = ldsw(Bl, rn + kb + 16);
#pragma unroll
            for (int mf = 0; mf < 2; mf++) {
                mma16816(acc[mf][nf], al[mf], bh0, bh1);   // lh
                mma16816(acc[mf][nf], ah[mf], bl0, bl1);   // hl
                mma16816(acc[mf][nf], am[mf], bm0, bm1);   // mm
                mma16816(acc[mf][nf], am[mf], bh0, bh1);   // mh
                mma16816(acc[mf][nf], ah[mf], bm0, bm1);   // hm
                mma16816(acc[mf][nf], ah[mf], bh0, bh1);   // hh
            }
        }
    }
}

__device__ __forceinline__ void hgemm_mainloop(
    const __nv_bfloat16* Ah, const __nv_bfloat16* Am, const __nv_bfloat16* Al, int lda,
    const __nv_bfloat16* Bh, const __nv_bfloat16* Bm, const __nv_bfloat16* Bl, int ldb,
    int nchunk, char* tiles, int tid, float acc[2][8][4])
{
    const int lane = tid & 31, wid = tid >> 5, wm = wid & 3, wn = wid >> 2;
#pragma unroll
    for (int i = 0; i < 2; i++)
#pragma unroll
        for (int j = 0; j < 8; j++)
#pragma unroll
            for (int r = 0; r < 4; r++) acc[i][j][r] = 0.f;

    uint32_t sb = smem_u32(tiles);
    stage_copy(Ah, Am, Al, lda, Bh, Bm, Bl, ldb, 0, sb, tid);
    CP_COMMIT();
    for (int c = 0; c < nchunk; c++) {
        if (c + 1 < nchunk) {
            stage_copy(Ah, Am, Al, lda, Bh, Bm, Bl, ldb, (c + 1) * 64,
                       sb + ((c + 1) & 1) * STG, tid);
            CP_COMMIT();
            CP_WAIT1();
        } else {
            CP_WAIT0();
        }
        __syncthreads();
        compute_chunk(tiles + (c & 1) * STG, lane, wm, wn, acc);
        __syncthreads();
    }
}

// ==================== convert x + Wv + Wo to bf16 h/m/l ====================
__global__ __launch_bounds__(256) void convert_wx(
    const float* __restrict__ x,
    const float* __restrict__ Wv, const float* __restrict__ Wo)
{
    const int total = (BB * NSEQ * DM + 2 * DM * DM) / 4;
    for (int idx = blockIdx.x * blockDim.x + threadIdx.x; idx < total;
         idx += gridDim.x * blockDim.x) {
        const float* src;
        __nv_bfloat16 *dh, *dm, *dl;
        int off;
        if (idx < (BB * NSEQ * DM) / 4) {
            src = x; dh = g_xh; dm = g_xm; dl = g_xl; off = idx;
        } else {
            int r = idx - (BB * NSEQ * DM) / 4;
            int w = r / ((DM * DM) / 4);
            off = r - w * ((DM * DM) / 4);
            src = (w == 0) ? Wv : Wo;
            dh = g_wh + (size_t)w * DM * DM;
            dm = g_wm + (size_t)w * DM * DM;
            dl = g_wl + (size_t)w * DM * DM;
        }
        float4 f = *(const float4*)(src + (size_t)off * 4);
        uint2 ph, pm, pl;
        split3(f.x, f.y, ph.x, pm.x, pl.x);
        split3(f.z, f.w, ph.y, pm.y, pl.y);
        *(uint2*)(dh + (size_t)off * 4) = ph;
        *(uint2*)(dm + (size_t)off * 4) = pm;
        *(uint2*)(dl + (size_t)off * 4) = pl;
    }
}

// ==================== V projection (HMMA): V = x Wv^T + bv -> fp32 =========
__global__ __launch_bounds__(256) void mma_v(const float* __restrict__ bv)
{
    extern __shared__ char smraw[];
    const uint32_t smb = smem_u32(smraw);
    char* tiles = smraw + (((smb + 1023) & ~1023u) - smb);
    const int tid = threadIdx.x, lane = tid & 31, wid = tid >> 5;
    const int g = lane >> 2, tig = lane & 3;
    const int wm = wid & 3, wn = wid >> 2;
    const int n0 = blockIdx.x * 128, m0 = blockIdx.y * 128;

    float acc[2][8][4];
    const size_t woff = (size_t)n0 * DM;           // Wv at segment 0
    hgemm_mainloop(g_xh + (size_t)m0 * DM, g_xm + (size_t)m0 * DM,
                   g_xl + (size_t)m0 * DM, DM,
                   g_wh + woff, g_wm + woff, g_wl + woff, DM,
                   16, tiles, tid, acc);

#pragma unroll
    for (int mf = 0; mf < 2; mf++)
#pragma unroll
        for (int nf = 0; nf < 8; nf++) {
            int n = n0 + wn * 64 + nf * 8 + tig * 2;
            int h = n >> 6, d = n & 63;
            float b0v = __ldg(&bv[n]), b1v = __ldg(&bv[n + 1]);
#pragma unroll
            for (int part = 0; part < 2; part++) {
                int m = m0 + wm * 32 + mf * 16 + g + part * 8;
                int bI = m >> 11, t = m & (NSEQ - 1);
                size_t base = (((size_t)(bI * NH + h)) * NSEQ + t) * DH + d;
                *(float2*)(g_v + base) =
                    make_float2(acc[mf][nf][part * 2 + 0] + b0v,
                                acc[mf][nf][part * 2 + 1] + b1v);
            }
        }
}

// ==================== output projection y = O Wo^T + bo (HMMA) =============
__global__ __launch_bounds__(256) void mma_out(
    const float* __restrict__ bo, float* __restrict__ y)
{
    extern __shared__ char smraw[];
    const uint32_t smb = smem_u32(smraw);
    char* tiles = smraw + (((smb + 1023) & ~1023u) - smb);
    const int tid = threadIdx.x, lane = tid & 31, wid = tid >> 5;
    const int g = lane >> 2, tig = lane & 3;
    const int wm = wid & 3, wn = wid >> 2;
    const int n0 = blockIdx.x * 128, m0 = blockIdx.y * 128;

    float acc[2][8][4];
    const size_t woff = (size_t)DM * DM + (size_t)n0 * DM;   // Wo at segment 1
    hgemm_mainloop(g_oh + (size_t)m0 * DM, g_om + (size_t)m0 * DM,
                   g_ol + (size_t)m0 * DM, DM,
                   g_wh + woff, g_wm + woff, g_wl + woff, DM,
                   16, tiles, tid, acc);

#pragma unroll
    for (int mf = 0; mf < 2; mf++)
#pragma unroll
        for (int nf = 0; nf < 8; nf++) {
            int n = n0 + wn * 64 + nf * 8 + tig * 2;
            float b0v = __ldg(&bo[n]), b1v = __ldg(&bo[n + 1]);
#pragma unroll
            for (int part = 0; part < 2; part++) {
                int m = m0 + wm * 32 + mf * 16 + g + part * 8;
                *(float2*)(y + (size_t)m * DM + n) =
                    make_float2(acc[mf][nf][part * 2 + 0] + b0v,
                                acc[mf][nf][part * 2 + 1] + b1v);
            }
        }
}

// ==================== zero fill ============================================
__global__ void zero_kernel(float4* __restrict__ p, int n4) {
    int i = blockIdx.x * blockDim.x + threadIdx.x;
    int stride = gridDim.x * blockDim.x;
    float4 z = make_float4(0.f, 0.f, 0.f, 0.f);
    for (; i < n4; i += stride) p[i] = z;
}

// ==================== Q,K projection GEMM (FFMA fp32, BK=32) ===============
// Bit-identical accumulation order to the BK=16 version (sequential k).
__global__ __launch_bounds__(256) void qkv_gemm_qk(
    const float* __restrict__ x,
    const float* __restrict__ Wq, const float* __restrict__ bq,
    const float* __restrict__ Wk, const float* __restrict__ bk)
{
    const float* W  = (blockIdx.z == 0) ? Wq : Wk;
    const float* bias = (blockIdx.z == 0) ? bq : bk;
    float* out = (blockIdx.z == 0) ? g_q : g_k;

    __shared__ float As[32][132];
    __shared__ float Bs[32][132];

    const int tid = threadIdx.x;
    const int m0 = blockIdx.y * 128;
    const int n0 = blockIdx.x * 128;
    const int r  = (tid / 16) * 4;
    const int c  = (tid % 16) * 4;
    const int lrow = tid >> 1;
    const int lk0  = (tid & 1) * 16;

    float acc[8][8];
#pragma unroll
    for (int i = 0; i < 8; i++)
#pragma unroll
        for (int j = 0; j < 8; j++) acc[i][j] = 0.f;

    for (int k0 = 0; k0 < DM; k0 += 32) {
#pragma unroll
        for (int t = 0; t < 4; t++) {
            float4 a = *(const float4*)&x[(size_t)(m0 + lrow) * DM + k0 + lk0 + t * 4];
            int kk = lk0 + t * 4;
            As[kk + 0][lrow] = a.x; As[kk + 1][lrow] = a.y;
            As[kk + 2][lrow] = a.z; As[kk + 3][lrow] = a.w;
            float4 b = *(const float4*)&W[(size_t)(n0 + lrow) * DM + k0 + lk0 + t * 4];
            Bs[kk + 0][lrow] = b.x; Bs[kk + 1][lrow] = b.y;
            Bs[kk + 2][lrow] = b.z; Bs[kk + 3][lrow] = b.w;
        }
        __syncthreads();
#pragma unroll
        for (int kk = 0; kk < 32; kk++) {
            float4 a0 = *(const float4*)&As[kk][r];
            float4 a1 = *(const float4*)&As[kk][r + 64];
            float4 b0 = *(const float4*)&Bs[kk][c];
            float4 b1 = *(const float4*)&Bs[kk][c + 64];
            float av[8] = {a0.x, a0.y, a0.z, a0.w, a1.x, a1.y, a1.z, a1.w};
            float bw[8] = {b0.x, b0.y, b0.z, b0.w, b1.x, b1.y, b1.z, b1.w};
#pragma unroll
            for (int i = 0; i < 8; i++)
#pragma unroll
                for (int j = 0; j < 8; j++) acc[i][j] += av[i] * bw[j];
        }
        __syncthreads();
    }

#pragma unroll
    for (int i = 0; i < 8; i++) {
        int m = m0 + ((i < 4) ? (r + i) : (r + 64 + i - 4));
        int bIdx = m >> 11;
        int t = m & (NSEQ - 1);
#pragma unroll
        for (int j = 0; j < 8; j++) {
            int n = n0 + ((j < 4) ? (c + j) : (c + 64 + j - 4));
            int h = n >> 6;
            int d = n & 63;
            out[(((size_t)(bIdx * NH + h)) * NSEQ + t) * DH + d] = acc[i][j] + bias[n];
        }
    }
}

// ==================== scores GEMM (FFMA fp32, BK=32) =======================
__global__ __launch_bounds__(256) void scores_gemm()
{
    int bx = blockIdx.x;
    int qt = 0;
    while ((qt + 1) * (qt + 2) / 2 <= bx) qt++;
    int kt = bx - qt * (qt + 1) / 2;
    const int bh = blockIdx.y;

    const float* Qb = g_q + (size_t)bh * NSEQ * DH;
    const float* Kb = g_k + (size_t)bh * NSEQ * DH;
    float* Sb = g_s + (size_t)bh * NSEQ * NSEQ;

    __shared__ float As[32][132];
    __shared__ float Bs[32][132];

    const int tid = threadIdx.x;
    const int q0 = qt * 128;
    const int k0b = kt * 128;
    const int r = (tid / 16) * 4;
    const int c = (tid % 16) * 4;
    const int lrow = tid >> 1;
    const int lk0  = (tid & 1) * 16;

    float acc[8][8];
#pragma unroll
    for (int i = 0; i < 8; i++)
#pragma unroll
        for (int j = 0; j < 8; j++) acc[i][j] = 0.f;

    for (int k0 = 0; k0 < DH; k0 += 32) {
#pragma unroll
        for (int t = 0; t < 4; t++) {
            float4 a = *(const float4*)&Qb[(size_t)(q0 + lrow) * DH + k0 + lk0 + t * 4];
            int kk = lk0 + t * 4;
            As[kk + 0][lrow] = a.x; As[kk + 1][lrow] = a.y;
            As[kk + 2][lrow] = a.z; As[kk + 3][lrow] = a.w;
            float4 b = *(const float4*)&Kb[(size_t)(k0b + lrow) * DH + k0 + lk0 + t * 4];
            Bs[kk + 0][lrow] = b.x; Bs[kk + 1][lrow] = b.y;
            Bs[kk + 2][lrow] = b.z; Bs[kk + 3][lrow] = b.w;
        }
        __syncthreads();
#pragma unroll
        for (int kk = 0; kk < 32; kk++) {
            float4 a0 = *(const float4*)&As[kk][r];
            float4 a1 = *(const float4*)&As[kk][r + 64];
            float4 b0 = *(const float4*)&Bs[kk][c];
            float4 b1 = *(const float4*)&Bs[kk][c + 64];
            float av[8] = {a0.x, a0.y, a0.z, a0.w, a1.x, a1.y, a1.z, a1.w};
            float bw[8] = {b0.x, b0.y, b0.z, b0.w, b1.x, b1.y, b1.z, b1.w};
#pragma unroll
            for (int i = 0; i < 8; i++)
#pragma unroll
                for (int j = 0; j < 8; j++) acc[i][j] += av[i] * bw[j];
        }
        __syncthreads();
    }

#pragma unroll
    for (int i = 0; i < 8; i++) {
        int q = q0 + ((i < 4) ? (r + i) : (r + 64 + i - 4));
#pragma unroll
        for (int j = 0; j < 8; j++) {
            int k = k0b + ((j < 4) ? (c + j) : (c + 64 + j - 4));
            float val = (k <= q) ? acc[i][j] * 0.125f : -INFINITY;
            Sb[(size_t)q * NSEQ + k] = val;
        }
    }
}

// ==================== topk helpers =========================================
__device__ __forceinline__ float warpSum(float v) {
#pragma unroll
    for (int o = 16; o; o >>= 1) v += __shfl_xor_sync(0xffffffffu, v, o);
    return v;
}
__device__ __forceinline__ void bsort32_desc(float& v, int& i, int lane) {
#pragma unroll
    for (int k = 2; k <= 32; k <<= 1) {
#pragma unroll
        for (int j = k >> 1; j > 0; j >>= 1) {
            float ov = __shfl_xor_sync(0xffffffffu, v, j);
            int   oi = __shfl_xor_sync(0xffffffffu, i, j);
            bool up    = ((lane & k) != 0);
            bool lower = ((lane & j) == 0);
            bool take  = (lower == up) ? (ov < v) : (ov > v);
            if (take) { v = ov; i = oi; }
        }
    }
}

// ==================== streaming warp top-32 + softmax + AV =================
__global__ __launch_bounds__(256) void topk_attn(float* __restrict__ attn_out)
{
    const int wid = (blockIdx.x * blockDim.x + threadIdx.x) >> 5;
    const int lane = threadIdx.x & 31;
    const int rowid = wid & (NSEQ - 1);
    const int bh = wid >> 11;
    const int q = (rowid & 1) ? (NSEQ - 1 - (rowid >> 1)) : (rowid >> 1);
    const int b = bh >> 4;
    const int h = bh & 15;

    const float* srow = g_s + ((size_t)bh * NSEQ + q) * NSEQ;
    const int nk = q + 1;

    float rv; int ri;
    float rmin;

    // ---- chunk 0: bulk init + insert rest
    {
        float4 v4 = *(const float4*)(srow + lane * 4);
        rv = v4.x; ri = lane * 4;
        bsort32_desc(rv, ri, lane);
        rmin = __shfl_sync(0xffffffffu, rv, 31);
#pragma unroll
        for (int t = 1; t < 4; t++) {
            float v = (t == 1) ? v4.y : (t == 2) ? v4.z : v4.w;
            unsigned m = __ballot_sync(0xffffffffu, v > rmin);
            while (m) {
                int src = __ffs(m) - 1;
                m &= m - 1;
                float val = __shfl_sync(0xffffffffu, v, src);
                if (val > rmin) {
                    int nidx = src * 4 + t;
                    bool gt = val > rv;
                    float pv = __shfl_up_sync(0xffffffffu, rv, 1);
                    int   pi = __shfl_up_sync(0xffffffffu, ri, 1);
                    unsigned gmask = __ballot_sync(0xffffffffu, gt);
                    int pos = __ffs(gmask) - 1;
                    if (gt) {
                        rv = (lane == pos) ? val : pv;
                        ri = (lane == pos) ? nidx : pi;
                    }
                    rmin = __shfl_sync(0xffffffffu, rv, 31);
                }
            }
        }
    }

    // ---- remaining chunks: one ballot per float4 group (local max4 filter)
    for (int c0 = 128; c0 < nk; c0 += 128) {
        float4 v4 = *(const float4*)(srow + c0 + lane * 4);
        float m4 = fmaxf(fmaxf(v4.x, v4.y), fmaxf(v4.z, v4.w));
        unsigned lanes = __ballot_sync(0xffffffffu, m4 > rmin);
        while (lanes) {
            int src = __ffs(lanes) - 1;
            lanes &= lanes - 1;
            float cand0 = __shfl_sync(0xffffffffu, v4.x, src);
            float cand1 = __shfl_sync(0xffffffffu, v4.y, src);
            float cand2 = __shfl_sync(0xffffffffu, v4.z, src);
            float cand3 = __shfl_sync(0xffffffffu, v4.w, src);
#pragma unroll
            for (int tt = 0; tt < 4; tt++) {
                float val = (tt == 0) ? cand0 : (tt == 1) ? cand1
                          : (tt == 2) ? cand2 : cand3;
                if (val > rmin) {                 // warp-uniform
                    int nidx = c0 + src * 4 + tt;
                    bool gt = val > rv;
                    float pv = __shfl_up_sync(0xffffffffu, rv, 1);
                    int   pi = __shfl_up_sync(0xffffffffu, ri, 1);
                    unsigned gmask = __ballot_sync(0xffffffffu, gt);
                    int pos = __ffs(gmask) - 1;
                    if (gt) {
                        rv = (lane == pos) ? val : pv;
                        ri = (lane == pos) ? nidx : pi;
                    }
                    rmin = __shfl_sync(0xffffffffu, rv, 31);
                }
            }
        }
    }

    float mx = __shfl_sync(0xffffffffu, rv, 0);
    float e = expf(rv - mx);
    float s = warpSum(e);
    float p = e / s;

    float acc0 = 0.f, acc1 = 0.f;
#pragma unroll 8
    for (int t = 0; t < 32; t++) {
        float pt = __shfl_sync(0xffffffffu, p, t);
        int   it = __shfl_sync(0xffffffffu, ri, t);
        if (pt > 0.f) {
            const float* vr = g_v + ((size_t)bh * NSEQ + it) * DH;
            acc0 += pt * vr[lane];
            acc1 += pt * vr[lane + 32];
        }
    }
    // O written as bf16 h/m/l (exact 24-bit split of the fp32 value)
    size_t obase = ((size_t)(b * NSEQ + q)) * DM + h * DH;
    {
        __nv_bfloat16 h0 = __float2bfloat16(acc0);
        float r0 = acc0 - __bfloat162float(h0);
        __nv_bfloat16 m0v = __float2bfloat16(r0);
        __nv_bfloat16 l0 = __float2bfloat16(r0 - __bfloat162float(m0v));
        g_oh[obase + lane] = h0; g_om[obase + lane] = m0v; g_ol[obase + lane] = l0;
        __nv_bfloat16 h1 = __float2bfloat16(acc1);
        float r1 = acc1 - __bfloat162float(h1);
        __nv_bfloat16 m1v = __float2bfloat16(r1);
        __nv_bfloat16 l1 = __float2bfloat16(r1 - __bfloat162float(m1v));
        g_oh[obase + lane + 32] = h1; g_om[obase + lane + 32] = m1v;
        g_ol[obase + lane + 32] = l1;
    }

    if (p > 0.f)
        atomicAdd(&attn_out[((size_t)b * NSEQ + q) * NSEQ + ri], p * (1.f / 16.f));
}

// ==================== launcher =============================================
extern "C" void kernel_launch(void* const* d_in, const int* in_sizes, int n_in,
                              void* d_out, int out_size)
{
    const float* x  = (const float*)d_in[0];
    const float* Wq = (const float*)d_in[1];
    const float* bq = (const float*)d_in[2];
    const float* Wk = (const float*)d_in[3];
    const float* bk = (const float*)d_in[4];
    const float* Wv = (const float*)d_in[5];
    const float* bv = (const float*)d_in[6];
    const float* Wo = (const float*)d_in[7];
    const float* bo = (const float*)d_in[8];

    float* out = (float*)d_out;
    const size_t y_elems = (size_t)BB * NSEQ * DM;
    const size_t a_elems = (size_t)BB * NSEQ * NSEQ;
    const bool has_attn = (size_t)out_size >= y_elems + a_elems;
    float* attn_ptr = has_attn ? (out + y_elems) : g_s;

    const int SM_2ST = 1024 + 2 * STG;
    cudaFuncSetAttribute(mma_v,   cudaFuncAttributeMaxDynamicSharedMemorySize, SM_2ST);
    cudaFuncSetAttribute(mma_out, cudaFuncAttributeMaxDynamicSharedMemorySize, SM_2ST);

    if (has_attn)
        zero_kernel<<<2048, 256>>>((float4*)attn_ptr, (int)(a_elems / 4));

    convert_wx<<<1024, 256>>>(x, Wv, Wo);

    dim3 g1(DM / 128, (BB * NSEQ) / 128, 2);               // Q, K (FFMA)
    qkv_gemm_qk<<<g1, 256>>>(x, Wq, bq, Wk, bk);

    dim3 gv(DM / 128, (BB * NSEQ) / 128);                  // V (HMMA)
    mma_v<<<gv, 256, SM_2ST>>>(bv);

    dim3 g2(136, BB * NH);
    scores_gemm<<<g2, 256>>>();

    topk_attn<<<(BB * NH * NSEQ) / 8, 256>>>(attn_ptr);

    dim3 g3(DM / 128, (BB * NSEQ) / 128);
    mma_out<<<g3, 256, SM_2ST>>>(bo, out);
}

// round 16
// speedup vs baseline: 1.4596x; 1.0569x over previous
#include <cuda_runtime.h>
#include <cuda_bf16.h>
#include <math.h>
#include <stdint.h>

#define BB 2
#define NSEQ 2048
#define NH 16
#define DH 64
#define DM 1024

// ---------------- scratch (device globals; no cudaMalloc allowed) ----------
__device__ float g_q[(size_t)BB * NH * NSEQ * DH];     // fp32 [bh][n][d]
__device__ float g_k[(size_t)BB * NH * NSEQ * DH];
__device__ float g_v[(size_t)BB * NH * NSEQ * DH];
__device__ float g_s[(size_t)BB * NH * NSEQ * NSEQ];   // 536 MB [bh][q][k]
// 2-way bf16 splits (h/l) for HMMA GEMMs (V projection + output projection)
__device__ __align__(16) __nv_bfloat16 g_xh[(size_t)BB * NSEQ * DM];
__device__ __align__(16) __nv_bfloat16 g_xl[(size_t)BB * NSEQ * DM];
__device__ __align__(16) __nv_bfloat16 g_wh[(size_t)2 * DM * DM];   // Wv, Wo
__device__ __align__(16) __nv_bfloat16 g_wl[(size_t)2 * DM * DM];
__device__ __align__(16) __nv_bfloat16 g_oh[(size_t)BB * NSEQ * DM];
__device__ __align__(16) __nv_bfloat16 g_ol[(size_t)BB * NSEQ * DM];

// stage layout: Ah@0 Al@16K Bh@32K Bl@48K ; stage = 64KB
#define RG 16384
#define STG 65536

// ==================== small helpers ========================================
__device__ __forceinline__ uint32_t smem_u32(const void* p) {
    uint32_t a;
    asm("{ .reg .u64 t; cvta.to.shared.u64 t, %1; cvt.u32.u64 %0, t; }"
        : "=r"(a) : "l"(p));
    return a;
}
__device__ __forceinline__ void cp16(uint32_t dst, const void* src) {
    asm volatile("cp.async.cg.shared.global [%0], [%1], 16;"
                 :: "r"(dst), "l"(src) : "memory");
}
#define CP_COMMIT() asm volatile("cp.async.commit_group;" ::: "memory")
#define CP_WAIT0()  asm volatile("cp.async.wait_group 0;" ::: "memory")
#define CP_WAIT1()  asm volatile("cp.async.wait_group 1;" ::: "memory")

__device__ __forceinline__ void mma16816(float* d, const uint32_t* a,
                                         uint32_t b0, uint32_t b1) {
    asm volatile(
        "mma.sync.aligned.m16n8k16.row.col.f32.bf16.bf16.f32 "
        "{%0,%1,%2,%3}, {%4,%5,%6,%7}, {%8,%9}, {%0,%1,%2,%3};"
        : "+f"(d[0]), "+f"(d[1]), "+f"(d[2]), "+f"(d[3])
        : "r"(a[0]), "r"(a[1]), "r"(a[2]), "r"(a[3]), "r"(b0), "r"(b1));
}
__device__ __forceinline__ uint32_t ldsw(const char* region, int off) {
    return *(const uint32_t*)(region + (off ^ ((off >> 3) & 0x70)));
}
__device__ __forceinline__ void split2(float a, float b, uint32_t& ph, uint32_t& pl) {
    __nv_bfloat162 h = __floats2bfloat162_rn(a, b);
    float ra = a - __bfloat162float(h.x);
    float rb = b - __bfloat162float(h.y);
    __nv_bfloat162 l = __floats2bfloat162_rn(ra, rb);
    ph = *(uint32_t*)&h; pl = *(uint32_t*)&l;
}

// ========== copy one K=64 chunk of A,B (h/l) into a 64KB smem stage ========
__device__ __forceinline__ void stage_copy(
    const __nv_bfloat16* __restrict__ Ah, const __nv_bfloat16* __restrict__ Al, int lda,
    const __nv_bfloat16* __restrict__ Bh, const __nv_bfloat16* __restrict__ Bl, int ldb,
    int kc, uint32_t sbase, int tid)
{
#pragma unroll
    for (int i = 0; i < 4; i++) {
        int u = tid + i * 256;
        int row = u >> 3;
        int cb = (u & 7) * 16;
        int off = row * 128 + cb;
        int sw = off ^ ((off >> 3) & 0x70);
        size_t ao = (size_t)row * lda + kc;
        size_t bo = (size_t)row * ldb + kc;
        cp16(sbase + 0 * RG + sw, (const char*)(Ah + ao) + cb);
        cp16(sbase + 1 * RG + sw, (const char*)(Al + ao) + cb);
        cp16(sbase + 2 * RG + sw, (const char*)(Bh + bo) + cb);
        cp16(sbase + 3 * RG + sw, (const char*)(Bl + bo) + cb);
    }
}

// ========== compute one K=64 chunk: acc += A(128x64) * B(128x64)^T =========
// 2-split, 3 products: lh, hl, hh  (error ~2^-18, fine for V/O path)
__device__ __forceinline__ void compute_chunk(
    const char* st, int lane, int wm, int wn, float acc[2][8][4])
{
    const int g = lane >> 2, tig = lane & 3;
    const char* Ah = st;
    const char* Al = st + 1 * RG;
    const char* Bh = st + 2 * RG;
    const char* Bl = st + 3 * RG;
#pragma unroll
    for (int ks = 0; ks < 4; ks++) {
        const int kb = ks * 32 + tig * 4;
        uint32_t ah[2][4], al[2][4];
#pragma unroll
        for (int mf = 0; mf < 2; mf++) {
            int r = (wm * 32 + mf * 16 + g) * 128;
            ah[mf][0] = ldsw(Ah, r + kb);
            ah[mf][1] = ldsw(Ah, r + 1024 + kb);
            ah[mf][2] = ldsw(Ah, r + kb + 16);
            ah[mf][3] = ldsw(Ah, r + 1024 + kb + 16);
            al[mf][0] = ldsw(Al, r + kb);
            al[mf][1] = ldsw(Al, r + 1024 + kb);
            al[mf][2] = ldsw(Al, r + kb + 16);
            al[mf][3] = ldsw(Al, r + 1024 + kb + 16);
        }
#pragma unroll
        for (int nf = 0; nf < 8; nf++) {
            int rn = (wn * 64 + nf * 8 + g) * 128;
            uint32_t bh0 = ldsw(Bh, rn + kb), bh1 = ldsw(Bh, rn + kb + 16);
            uint32_t bl0 = ldsw(Bl, rn + kb), bl1 = ldsw(Bl, rn + kb + 16);
#pragma unroll
            for (int mf = 0; mf < 2; mf++) {
                mma16816(acc[mf][nf], al[mf], bh0, bh1);   // lh
                mma16816(acc[mf][nf], ah[mf], bl0, bl1);   // hl
                mma16816(acc[mf][nf], ah[mf], bh0, bh1);   // hh
            }
        }
    }
}

__device__ __forceinline__ void hgemm_mainloop(
    const __nv_bfloat16* Ah, const __nv_bfloat16* Al, int lda,
    const __nv_bfloat16* Bh, const __nv_bfloat16* Bl, int ldb,
    int nchunk, char* tiles, int tid, float acc[2][8][4])
{
    const int lane = tid & 31, wid = tid >> 5, wm = wid & 3, wn = wid >> 2;
#pragma unroll
    for (int i = 0; i < 2; i++)
#pragma unroll
        for (int j = 0; j < 8; j++)
#pragma unroll
            for (int r = 0; r < 4; r++) acc[i][j][r] = 0.f;

    uint32_t sb = smem_u32(tiles);
    stage_copy(Ah, Al, lda, Bh, Bl, ldb, 0, sb, tid);
    CP_COMMIT();
    for (int c = 0; c < nchunk; c++) {
        if (c + 1 < nchunk) {
            stage_copy(Ah, Al, lda, Bh, Bl, ldb, (c + 1) * 64,
                       sb + ((c + 1) & 1) * STG, tid);
            CP_COMMIT();
            CP_WAIT1();
        } else {
            CP_WAIT0();
        }
        __syncthreads();
        compute_chunk(tiles + (c & 1) * STG, lane, wm, wn, acc);
        __syncthreads();
    }
}

// ==================== convert x + Wv + Wo to bf16 h/l ======================
__global__ __launch_bounds__(256) void convert_wx(
    const float* __restrict__ x,
    const float* __restrict__ Wv, const float* __restrict__ Wo)
{
    const int total = (BB * NSEQ * DM + 2 * DM * DM) / 4;
    for (int idx = blockIdx.x * blockDim.x + threadIdx.x; idx < total;
         idx += gridDim.x * blockDim.x) {
        const float* src;
        __nv_bfloat16 *dh, *dl;
        int off;
        if (idx < (BB * NSEQ * DM) / 4) {
            src = x; dh = g_xh; dl = g_xl; off = idx;
        } else {
            int r = idx - (BB * NSEQ * DM) / 4;
            int w = r / ((DM * DM) / 4);
            off = r - w * ((DM * DM) / 4);
            src = (w == 0) ? Wv : Wo;
            dh = g_wh + (size_t)w * DM * DM;
            dl = g_wl + (size_t)w * DM * DM;
        }
        float4 f = *(const float4*)(src + (size_t)off * 4);
        uint2 ph, pl;
        split2(f.x, f.y, ph.x, pl.x);
        split2(f.z, f.w, ph.y, pl.y);
        *(uint2*)(dh + (size_t)off * 4) = ph;
        *(uint2*)(dl + (size_t)off * 4) = pl;
    }
}

// ==================== V projection (HMMA): V = x Wv^T + bv -> fp32 =========
__global__ __launch_bounds__(256) void mma_v(const float* __restrict__ bv)
{
    extern __shared__ char smraw[];
    const uint32_t smb = smem_u32(smraw);
    char* tiles = smraw + (((smb + 1023) & ~1023u) - smb);
    const int tid = threadIdx.x, lane = tid & 31, wid = tid >> 5;
    const int g = lane >> 2, tig = lane & 3;
    const int wm = wid & 3, wn = wid >> 2;
    const int n0 = blockIdx.x * 128, m0 = blockIdx.y * 128;

    float acc[2][8][4];
    const size_t woff = (size_t)n0 * DM;           // Wv at segment 0
    hgemm_mainloop(g_xh + (size_t)m0 * DM, g_xl + (size_t)m0 * DM, DM,
                   g_wh + woff, g_wl + woff, DM,
                   16, tiles, tid, acc);

#pragma unroll
    for (int mf = 0; mf < 2; mf++)
#pragma unroll
        for (int nf = 0; nf < 8; nf++) {
            int n = n0 + wn * 64 + nf * 8 + tig * 2;
            int h = n >> 6, d = n & 63;
            float b0v = __ldg(&bv[n]), b1v = __ldg(&bv[n + 1]);
#pragma unroll
            for (int part = 0; part < 2; part++) {
                int m = m0 + wm * 32 + mf * 16 + g + part * 8;
                int bI = m >> 11, t = m & (NSEQ - 1);
                size_t base = (((size_t)(bI * NH + h)) * NSEQ + t) * DH + d;
                *(float2*)(g_v + base) =
                    make_float2(acc[mf][nf][part * 2 + 0] + b0v,
                                acc[mf][nf][part * 2 + 1] + b1v);
            }
        }
}

// ==================== output projection y = O Wo^T + bo (HMMA) =============
__global__ __launch_bounds__(256) void mma_out(
    const float* __restrict__ bo, float* __restrict__ y)
{
    extern __shared__ char smraw[];
    const uint32_t smb = smem_u32(smraw);
    char* tiles = smraw + (((smb + 1023) & ~1023u) - smb);
    const int tid = threadIdx.x, lane = tid & 31, wid = tid >> 5;
    const int g = lane >> 2, tig = lane & 3;
    const int wm = wid & 3, wn = wid >> 2;
    const int n0 = blockIdx.x * 128, m0 = blockIdx.y * 128;

    float acc[2][8][4];
    const size_t woff = (size_t)DM * DM + (size_t)n0 * DM;   // Wo at segment 1
    hgemm_mainloop(g_oh + (size_t)m0 * DM, g_ol + (size_t)m0 * DM, DM,
                   g_wh + woff, g_wl + woff, DM,
                   16, tiles, tid, acc);

#pragma unroll
    for (int mf = 0; mf < 2; mf++)
#pragma unroll
        for (int nf = 0; nf < 8; nf++) {
            int n = n0 + wn * 64 + nf * 8 + tig * 2;
            float b0v = __ldg(&bo[n]), b1v = __ldg(&bo[n + 1]);
#pragma unroll
            for (int part = 0; part < 2; part++) {
                int m = m0 + wm * 32 + mf * 16 + g + part * 8;
                *(float2*)(y + (size_t)m * DM + n) =
                    make_float2(acc[mf][nf][part * 2 + 0] + b0v,
                                acc[mf][nf][part * 2 + 1] + b1v);
            }
        }
}

// ==================== zero fill ============================================
__global__ void zero_kernel(float4* __restrict__ p, int n4) {
    int i = blockIdx.x * blockDim.x + threadIdx.x;
    int stride = gridDim.x * blockDim.x;
    float4 z = make_float4(0.f, 0.f, 0.f, 0.f);
    for (; i < n4; i += stride) p[i] = z;
}

// ==================== Q,K projection GEMM (FFMA fp32, BK=32; FROZEN) =======
__global__ __launch_bounds__(256) void qkv_gemm_qk(
    const float* __restrict__ x,
    const float* __restrict__ Wq, const float* __restrict__ bq,
    const float* __restrict__ Wk, const float* __restrict__ bk)
{
    const float* W  = (blockIdx.z == 0) ? Wq : Wk;
    const float* bias = (blockIdx.z == 0) ? bq : bk;
    float* out = (blockIdx.z == 0) ? g_q : g_k;

    __shared__ float As[32][132];
    __shared__ float Bs[32][132];

    const int tid = threadIdx.x;
    const int m0 = blockIdx.y * 128;
    const int n0 = blockIdx.x * 128;
    const int r  = (tid / 16) * 4;
    const int c  = (tid % 16) * 4;
    const int lrow = tid >> 1;
    const int lk0  = (tid & 1) * 16;

    float acc[8][8];
#pragma unroll
    for (int i = 0; i < 8; i++)
#pragma unroll
        for (int j = 0; j < 8; j++) acc[i][j] = 0.f;

    for (int k0 = 0; k0 < DM; k0 += 32) {
#pragma unroll
        for (int t = 0; t < 4; t++) {
            float4 a = *(const float4*)&x[(size_t)(m0 + lrow) * DM + k0 + lk0 + t * 4];
            int kk = lk0 + t * 4;
            As[kk + 0][lrow] = a.x; As[kk + 1][lrow] = a.y;
            As[kk + 2][lrow] = a.z; As[kk + 3][lrow] = a.w;
            float4 b = *(const float4*)&W[(size_t)(n0 + lrow) * DM + k0 + lk0 + t * 4];
            Bs[kk + 0][lrow] = b.x; Bs[kk + 1][lrow] = b.y;
            Bs[kk + 2][lrow] = b.z; Bs[kk + 3][lrow] = b.w;
        }
        __syncthreads();
#pragma unroll
        for (int kk = 0; kk < 32; kk++) {
            float4 a0 = *(const float4*)&As[kk][r];
            float4 a1 = *(const float4*)&As[kk][r + 64];
            float4 b0 = *(const float4*)&Bs[kk][c];
            float4 b1 = *(const float4*)&Bs[kk][c + 64];
            float av[8] = {a0.x, a0.y, a0.z, a0.w, a1.x, a1.y, a1.z, a1.w};
            float bw[8] = {b0.x, b0.y, b0.z, b0.w, b1.x, b1.y, b1.z, b1.w};
#pragma unroll
            for (int i = 0; i < 8; i++)
#pragma unroll
                for (int j = 0; j < 8; j++) acc[i][j] += av[i] * bw[j];
        }
        __syncthreads();
    }

#pragma unroll
    for (int i = 0; i < 8; i++) {
        int m = m0 + ((i < 4) ? (r + i) : (r + 64 + i - 4));
        int bIdx = m >> 11;
        int t = m & (NSEQ - 1);
#pragma unroll
        for (int j = 0; j < 8; j++) {
            int n = n0 + ((j < 4) ? (c + j) : (c + 64 + j - 4));
            int h = n >> 6;
            int d = n & 63;
            out[(((size_t)(bIdx * NH + h)) * NSEQ + t) * DH + d] = acc[i][j] + bias[n];
        }
    }
}

// ==================== scores GEMM (FFMA fp32, BK=32; FROZEN) ===============
__global__ __launch_bounds__(256) void scores_gemm()
{
    int bx = blockIdx.x;
    int qt = 0;
    while ((qt + 1) * (qt + 2) / 2 <= bx) qt++;
    int kt = bx - qt * (qt + 1) / 2;
    const int bh = blockIdx.y;

    const float* Qb = g_q + (size_t)bh * NSEQ * DH;
    const float* Kb = g_k + (size_t)bh * NSEQ * DH;
    float* Sb = g_s + (size_t)bh * NSEQ * NSEQ;

    __shared__ float As[32][132];
    __shared__ float Bs[32][132];

    const int tid = threadIdx.x;
    const int q0 = qt * 128;
    const int k0b = kt * 128;
    const int r = (tid / 16) * 4;
    const int c = (tid % 16) * 4;
    const int lrow = tid >> 1;
    const int lk0  = (tid & 1) * 16;

    float acc[8][8];
#pragma unroll
    for (int i = 0; i < 8; i++)
#pragma unroll
        for (int j = 0; j < 8; j++) acc[i][j] = 0.f;

    for (int k0 = 0; k0 < DH; k0 += 32) {
#pragma unroll
        for (int t = 0; t < 4; t++) {
            float4 a = *(const float4*)&Qb[(size_t)(q0 + lrow) * DH + k0 + lk0 + t * 4];
            int kk = lk0 + t * 4;
            As[kk + 0][lrow] = a.x; As[kk + 1][lrow] = a.y;
            As[kk + 2][lrow] = a.z; As[kk + 3][lrow] = a.w;
            float4 b = *(const float4*)&Kb[(size_t)(k0b + lrow) * DH + k0 + lk0 + t * 4];
            Bs[kk + 0][lrow] = b.x; Bs[kk + 1][lrow] = b.y;
            Bs[kk + 2][lrow] = b.z; Bs[kk + 3][lrow] = b.w;
        }
        __syncthreads();
#pragma unroll
        for (int kk = 0; kk < 32; kk++) {
            float4 a0 = *(const float4*)&As[kk][r];
            float4 a1 = *(const float4*)&As[kk][r + 64];
            float4 b0 = *(const float4*)&Bs[kk][c];
            float4 b1 = *(const float4*)&Bs[kk][c + 64];
            float av[8] = {a0.x, a0.y, a0.z, a0.w, a1.x, a1.y, a1.z, a1.w};
            float bw[8] = {b0.x, b0.y, b0.z, b0.w, b1.x, b1.y, b1.z, b1.w};
#pragma unroll
            for (int i = 0; i < 8; i++)
#pragma unroll
                for (int j = 0; j < 8; j++) acc[i][j] += av[i] * bw[j];
        }
        __syncthreads();
    }

#pragma unroll
    for (int i = 0; i < 8; i++) {
        int q = q0 + ((i < 4) ? (r + i) : (r + 64 + i - 4));
#pragma unroll
        for (int j = 0; j < 8; j++) {
            int k = k0b + ((j < 4) ? (c + j) : (c + 64 + j - 4));
            float val = (k <= q) ? acc[i][j] * 0.125f : -INFINITY;
            Sb[(size_t)q * NSEQ + k] = val;
        }
    }
}

// ==================== topk helpers =========================================
__device__ __forceinline__ float warpSum(float v) {
#pragma unroll
    for (int o = 16; o; o >>= 1) v += __shfl_xor_sync(0xffffffffu, v, o);
    return v;
}
__device__ __forceinline__ void bsort32_desc(float& v, int& i, int lane) {
#pragma unroll
    for (int k = 2; k <= 32; k <<= 1) {
#pragma unroll
        for (int j = k >> 1; j > 0; j >>= 1) {
            float ov = __shfl_xor_sync(0xffffffffu, v, j);
            int   oi = __shfl_xor_sync(0xffffffffu, i, j);
            bool up    = ((lane & k) != 0);
            bool lower = ((lane & j) == 0);
            bool take  = (lower == up) ? (ov < v) : (ov > v);
            if (take) { v = ov; i = oi; }
        }
    }
}
// shift-insert val/idx into descending warp list (caller guarantees val > rmin)
#define TOPK_INSERT(val, nidx)                                             \
    do {                                                                   \
        bool gt = (val) > rv;                                              \
        float pv = __shfl_up_sync(0xffffffffu, rv, 1);                     \
        int   pi = __shfl_up_sync(0xffffffffu, ri, 1);                     \
        unsigned gmask = __ballot_sync(0xffffffffu, gt);                   \
        int pos = __ffs(gmask) - 1;                                        \
        if (gt) {                                                          \
            rv = (lane == pos) ? (val) : pv;                               \
            ri = (lane == pos) ? (nidx) : pi;                              \
        }                                                                  \
        rmin = __shfl_sync(0xffffffffu, rv, 31);                           \
    } while (0)

// ==================== streaming warp top-32 + softmax + AV =================
__global__ __launch_bounds__(256) void topk_attn(float* __restrict__ attn_out)
{
    const int wid = (blockIdx.x * blockDim.x + threadIdx.x) >> 5;
    const int lane = threadIdx.x & 31;
    const int rowid = wid & (NSEQ - 1);
    const int bh = wid >> 11;
    const int q = (rowid & 1) ? (NSEQ - 1 - (rowid >> 1)) : (rowid >> 1);
    const int b = bh >> 4;
    const int h = bh & 15;

    const float* srow = g_s + ((size_t)bh * NSEQ + q) * NSEQ;
    const int nk = q + 1;

    float rv; int ri;
    float rmin;

    // ---- chunk 0: bulk init + insert rest
    {
        float4 v4 = *(const float4*)(srow + lane * 4);
        rv = v4.x; ri = lane * 4;
        bsort32_desc(rv, ri, lane);
        rmin = __shfl_sync(0xffffffffu, rv, 31);
#pragma unroll
        for (int t = 1; t < 4; t++) {
            float v = (t == 1) ? v4.y : (t == 2) ? v4.z : v4.w;
            unsigned m = __ballot_sync(0xffffffffu, v > rmin);
            while (m) {
                int src = __ffs(m) - 1;
                m &= m - 1;
                float val = __shfl_sync(0xffffffffu, v, src);
                if (val > rmin) {
                    int nidx = src * 4 + t;
                    TOPK_INSERT(val, nidx);
                }
            }
        }
    }

    // ---- double chunks: one ballot per 8 elements (two float4 per lane)
    int c0 = 128;
    for (; c0 + 128 < nk; c0 += 256) {
        float4 va = *(const float4*)(srow + c0 + lane * 4);
        float4 vb = *(const float4*)(srow + c0 + 128 + lane * 4);
        float m8 = fmaxf(fmaxf(fmaxf(va.x, va.y), fmaxf(va.z, va.w)),
                         fmaxf(fmaxf(vb.x, vb.y), fmaxf(vb.z, vb.w)));
        unsigned lanes = __ballot_sync(0xffffffffu, m8 > rmin);
        while (lanes) {
            int src = __ffs(lanes) - 1;
            lanes &= lanes - 1;
            float c0v = __shfl_sync(0xffffffffu, va.x, src);
            float c1v = __shfl_sync(0xffffffffu, va.y, src);
            float c2v = __shfl_sync(0xffffffffu, va.z, src);
            float c3v = __shfl_sync(0xffffffffu, va.w, src);
            float c4v = __shfl_sync(0xffffffffu, vb.x, src);
            float c5v = __shfl_sync(0xffffffffu, vb.y, src);
            float c6v = __shfl_sync(0xffffffffu, vb.z, src);
            float c7v = __shfl_sync(0xffffffffu, vb.w, src);
#pragma unroll
            for (int tt = 0; tt < 8; tt++) {
                float val = (tt == 0) ? c0v : (tt == 1) ? c1v : (tt == 2) ? c2v
                          : (tt == 3) ? c3v : (tt == 4) ? c4v : (tt == 5) ? c5v
                          : (tt == 6) ? c6v : c7v;
                if (val > rmin) {
                    int nidx = c0 + ((tt >= 4) ? 128 : 0) + src * 4 + (tt & 3);
                    TOPK_INSERT(val, nidx);
                }
            }
        }
    }
    // ---- tail single chunk (at most one)
    for (; c0 < nk; c0 += 128) {
        float4 v4 = *(const float4*)(srow + c0 + lane * 4);
        float m4 = fmaxf(fmaxf(v4.x, v4.y), fmaxf(v4.z, v4.w));
        unsigned lanes = __ballot_sync(0xffffffffu, m4 > rmin);
        while (lanes) {
            int src = __ffs(lanes) - 1;
            lanes &= lanes - 1;
            float c0v = __shfl_sync(0xffffffffu, v4.x, src);
            float c1v = __shfl_sync(0xffffffffu, v4.y, src);
            float c2v = __shfl_sync(0xffffffffu, v4.z, src);
            float c3v = __shfl_sync(0xffffffffu, v4.w, src);
#pragma unroll
            for (int tt = 0; tt < 4; tt++) {
                float val = (tt == 0) ? c0v : (tt == 1) ? c1v
                          : (tt == 2) ? c2v : c3v;
                if (val > rmin) {
                    int nidx = c0 + src * 4 + tt;
                    TOPK_INSERT(val, nidx);
                }
            }
        }
    }

    float mx = __shfl_sync(0xffffffffu, rv, 0);
    float e = expf(rv - mx);
    float s = warpSum(e);
    float p = e / s;

    float acc0 = 0.f, acc1 = 0.f;
#pragma unroll 8
    for (int t = 0; t < 32; t++) {
        float pt = __shfl_sync(0xffffffffu, p, t);
        int   it = __shfl_sync(0xffffffffu, ri, t);
        if (pt > 0.f) {
            const float* vr = g_v + ((size_t)bh * NSEQ + it) * DH;
            acc0 += pt * vr[lane];
            acc1 += pt * vr[lane + 32];
        }
    }
    // O written as bf16 h/l (2-split; y error contribution ~4e-6)
    size_t obase = ((size_t)(b * NSEQ + q)) * DM + h * DH;
    {
        __nv_bfloat16 h0 = __float2bfloat16(acc0);
        g_oh[obase + lane] = h0;
        g_ol[obase + lane] = __float2bfloat16(acc0 - __bfloat162float(h0));
        __nv_bfloat16 h1 = __float2bfloat16(acc1);
        g_oh[obase + lane + 32] = h1;
        g_ol[obase + lane + 32] = __float2bfloat16(acc1 - __bfloat162float(h1));
    }

    if (p > 0.f)
        atomicAdd(&attn_out[((size_t)b * NSEQ + q) * NSEQ + ri], p * (1.f / 16.f));
}

// ==================== launcher =============================================
extern "C" void kernel_launch(void* const* d_in, const int* in_sizes, int n_in,
                              void* d_out, int out_size)
{
    const float* x  = (const float*)d_in[0];
    const float* Wq = (const float*)d_in[1];
    const float* bq = (const float*)d_in[2];
    const float* Wk = (const float*)d_in[3];
    const float* bk = (const float*)d_in[4];
    const float* Wv = (const float*)d_in[5];
    const float* bv = (const float*)d_in[6];
    const float* Wo = (const float*)d_in[7];
    const float* bo = (const float*)d_in[8];

    float* out = (float*)d_out;
    const size_t y_elems = (size_t)BB * NSEQ * DM;
    const size_t a_elems = (size_t)BB * NSEQ * NSEQ;
    const bool has_attn = (size_t)out_size >= y_elems + a_elems;
    float* attn_ptr = has_attn ? (out + y_elems) : g_s;

    const int SM_2ST = 1024 + 2 * STG;     // 132096
    cudaFuncSetAttribute(mma_v,   cudaFuncAttributeMaxDynamicSharedMemorySize, SM_2ST);
    cudaFuncSetAttribute(mma_out, cudaFuncAttributeMaxDynamicSharedMemorySize, SM_2ST);

    if (has_attn)
        zero_kernel<<<2048, 256>>>((float4*)attn_ptr, (int)(a_elems / 4));

    convert_wx<<<1024, 256>>>(x, Wv, Wo);

    dim3 g1(DM / 128, (BB * NSEQ) / 128, 2);               // Q, K (FFMA)
    qkv_gemm_qk<<<g1, 256>>>(x, Wq, bq, Wk, bk);

    dim3 gv(DM / 128, (BB * NSEQ) / 128);                  // V (HMMA 2-split)
    mma_v<<<gv, 256, SM_2ST>>>(bv);

    dim3 g2(136, BB * NH);
    scores_gemm<<<g2, 256>>>();

    topk_attn<<<(BB * NH * NSEQ) / 8, 256>>>(attn_ptr);

    dim3 g3(DM / 128, (BB * NSEQ) / 128);                  // y (HMMA 2-split)
    mma_out<<<g3, 256, SM_2ST>>>(bo, out);
}